// round 2
// baseline (speedup 1.0000x reference)
#include <cuda_runtime.h>
#include <math.h>
#include <float.h>

// Problem capacities (B=32, N=300, M=60, L=5, C=1000)
#define CAP_B 32
#define CAP_N 300
#define CAP_M 60
#define QMAX 10            // ceil(300/32) columns per lane
#define BCE_CAP_BLOCKS 512

// ---------------- device scratch (no allocations allowed) ----------------
__device__ float    g_cost[CAP_B * CAP_M * CAP_N];  // [b][t][j]
__device__ int      g_k[CAP_B];
__device__ float    g_obj_t[CAP_B * CAP_N];
__device__ double   g_cls[CAP_B];
__device__ double   g_pair[CAP_B * 4];              // {bbox, giou, aux_bbox, aux_giou}
__device__ double   g_bce[BCE_CAP_BLOCKS * 2];
__device__ unsigned g_sem;

// ---------------- helpers ----------------
__device__ __forceinline__ float giou_f(
    float ax0, float ay0, float ax1, float ay1,
    float bx0, float by0, float bx1, float by1)
{
    const float EPS = 1e-7f;
    float area_a = (ax1 - ax0) * (ay1 - ay0);
    float area_b = (bx1 - bx0) * (by1 - by0);
    float ltx = fmaxf(ax0, bx0), lty = fmaxf(ay0, by0);
    float rbx = fminf(ax1, bx1), rby = fminf(ay1, by1);
    float wx = fmaxf(rbx - ltx, 0.0f), wy = fmaxf(rby - lty, 0.0f);
    float inter = wx * wy;
    float uni = area_a + area_b - inter;
    float iou = inter / (uni + EPS);
    float ex = fmaxf(fmaxf(ax1, bx1) - fminf(ax0, bx0), 0.0f);
    float ey = fmaxf(fmaxf(ay1, by1) - fminf(ay0, by0), 0.0f);
    float enc = ex * ey;
    return iou - (enc - uni) / (enc + EPS);
}

__device__ __forceinline__ float giou_cxcywh(float4 p, float4 q)
{
    return giou_f(p.x - p.z * 0.5f, p.y - p.w * 0.5f, p.x + p.z * 0.5f, p.y + p.w * 0.5f,
                  q.x - q.z * 0.5f, q.y - q.w * 0.5f, q.x + q.z * 0.5f, q.y + q.w * 0.5f);
}

__device__ __forceinline__ float l1_cxcywh(float4 p, float4 q)
{
    return fabsf(p.x - q.x) + fabsf(p.y - q.y) + fabsf(p.z - q.z) + fabsf(p.w - q.w);
}

__device__ __forceinline__ float bce_f(float x, float t)
{
    return fmaxf(x, 0.0f) - x * t + log1pf(expf(-fabsf(x)));
}

// ordered mappings (ascending)
__device__ __forceinline__ unsigned order_f32(float f)
{
    unsigned u = __float_as_uint(f);
    return (u & 0x80000000u) ? ~u : (u | 0x80000000u);
}
__device__ __forceinline__ unsigned long long order_f64(double d)
{
    long long ll = __double_as_longlong(d);
    return (ll < 0) ? ~(unsigned long long)ll
                    : ((unsigned long long)ll | 0x8000000000000000ull);
}
__device__ __forceinline__ double unorder_f64(unsigned long long k)
{
    long long ll = (k & 0x8000000000000000ull) ? (long long)(k ^ 0x8000000000000000ull)
                                               : (long long)(~k);
    return __longlong_as_double(ll);
}

// ---------------- K1: cost matrix + cls loss + init ----------------
__global__ void prep_kernel(const float4* __restrict__ pred,
                            const float4* __restrict__ tgt,
                            const float* __restrict__ cls,
                            const int* __restrict__ label,
                            int B, int N, int M, int C, int cost_blocks)
{
    __shared__ float sred[256];
    if ((int)blockIdx.x < cost_blocks) {
        int idx = blockIdx.x * 256 + threadIdx.x;
        if (idx == 0) g_sem = 0u;
        if (idx < B * N) g_obj_t[idx] = 0.0f;
        int total = B * M * N;
        if (idx < total) {
            int j = idx % N;
            int t = (idx / N) % M;
            int b = idx / (N * M);
            float4 p = pred[b * N + j];
            float4 q = tgt[b * M + t];
            g_cost[idx] = 5.0f * l1_cxcywh(p, q) - 2.0f * giou_cxcywh(p, q);
        }
    } else {
        int b = blockIdx.x - cost_blocks;
        int tid = threadIdx.x;
        const float* x = cls + (size_t)b * C;
        float m = -FLT_MAX;
        for (int c = tid; c < C; c += 256) m = fmaxf(m, x[c]);
        sred[tid] = m;
        __syncthreads();
        for (int off = 128; off; off >>= 1) {
            if (tid < off) sred[tid] = fmaxf(sred[tid], sred[tid + off]);
            __syncthreads();
        }
        m = sred[0];
        __syncthreads();
        float s = 0.0f;
        for (int c = tid; c < C; c += 256) s += expf(x[c] - m);
        sred[tid] = s;
        __syncthreads();
        for (int off = 128; off; off >>= 1) {
            if (tid < off) sred[tid] += sred[tid + off];
            __syncthreads();
        }
        if (tid == 0) g_cls[b] = (double)(m + logf(sred[0]) - x[label[b]]);
    }
}

// ---------------- K2: LAPJV (greedy init + sparse augmentation) + pair losses ----------------
// One block of 128 threads per batch. Greedy phase uses all 4 warps;
// Dijkstra augmentation runs on warp 0 (warp-synchronous, register-resident duals).
__global__ void __launch_bounds__(128, 1)
hungarian_kernel(const float* __restrict__ mask,
                 const float4* __restrict__ pred,
                 const float4* __restrict__ tgt,
                 const float4* __restrict__ aux_pred,
                 int B, int N, int M, int L)
{
    const unsigned FULL = 0xffffffffu;
    int b = blockIdx.x;
    int tid = threadIdx.x;
    int lane = tid & 31, wid = tid >> 5;

    __shared__ double u_sh[CAP_M + 2];
    __shared__ int p_sh[CAP_N + 1];       // column j (1..N) -> row (1-based), 0 = free
    __shared__ int way_sh[CAP_N + 1];
    __shared__ int vid_sh[CAP_M];
    __shared__ int gcol_sh[CAP_M];        // greedy argmin column per row
    __shared__ int rowcol_sh[CAP_M];      // resolved greedy col or -1
    __shared__ int s_k;
    __shared__ double s_red[16];

    for (int j = tid; j <= N; j += 128) { p_sh[j] = 0; way_sh[j] = 0; }
    for (int r = tid; r <= M; r += 128) u_sh[r] = 0.0;

    const float* mrow = mask + (size_t)b * M;
    if (wid == 0) {
        bool v0 = (lane < M) && (mrow[lane] > 0.5f);
        bool v1 = (32 + lane < M) && (mrow[32 + lane] > 0.5f);
        unsigned b0 = __ballot_sync(FULL, v0);
        unsigned b1 = __ballot_sync(FULL, v1);
        unsigned lm = (1u << lane) - 1u;
        if (v0) vid_sh[__popc(b0 & lm)] = lane;
        if (v1) vid_sh[__popc(b0) + __popc(b1 & lm)] = 32 + lane;
        if (lane == 0) {
            s_k = __popc(b0) + __popc(b1);
            g_k[b] = s_k;
        }
    }
    __syncthreads();
    int k = s_k;
    const float* cb = g_cost + (size_t)b * M * N;

    // --- greedy phase: row minima + argmin columns (rows striped over 4 warps) ---
    for (int i = wid; i < k; i += 4) {
        const float* crow = cb + (size_t)vid_sh[i] * N;
        float bf = INFINITY;
        int bc = N;
        #pragma unroll
        for (int q = 0; q < QMAX; q++) {
            int col = lane + 32 * q;
            if (col < N) {
                float c = crow[col];
                if (c < bf) { bf = c; bc = col; }
            }
        }
        unsigned key = order_f32(bf);
        unsigned rmin = __reduce_min_sync(FULL, key);
        unsigned cand = (key == rmin) ? (unsigned)bc : 0xFFFFFFFFu;
        unsigned cmin = __reduce_min_sync(FULL, cand);
        if (key == rmin && (unsigned)bc == cmin) {
            u_sh[i + 1] = (double)bf;
            gcol_sh[i] = bc;
        }
    }
    __syncthreads();

    // serial deterministic conflict resolution
    if (tid == 0) {
        for (int i = 0; i < k; i++) {
            int c = gcol_sh[i];
            if (p_sh[c + 1] == 0) { p_sh[c + 1] = i + 1; rowcol_sh[i] = c; }
            else rowcol_sh[i] = -1;
        }
    }
    __syncthreads();

    // --- Dijkstra augmentation for unassigned rows (warp 0 only) ---
    if (wid == 0) {
        double v[QMAX];
        #pragma unroll
        for (int q = 0; q < QMAX; q++) v[q] = 0.0;

        for (int i = 0; i < k; i++) {
            if (rowcol_sh[i] >= 0) continue;
            int f = i + 1;
            double minv[QMAX];
            #pragma unroll
            for (int q = 0; q < QMAX; q++) minv[q] = INFINITY;
            unsigned usedmask = 0;
            if (lane == 0) p_sh[0] = f;
            __syncwarp();
            int j0 = 0;
            while (true) {
                if (j0 > 0 && ((j0 - 1) & 31) == lane)
                    usedmask |= 1u << ((j0 - 1) >> 5);
                int i0 = p_sh[j0];
                double ui0 = u_sh[i0];
                const float* crow = cb + (size_t)vid_sh[i0 - 1] * N;
                double bval = INFINITY;
                int bj = N + 1;
                #pragma unroll
                for (int q = 0; q < QMAX; q++) {
                    int col = lane + 32 * q;
                    if (col < N && !(usedmask & (1u << q))) {
                        double cur = (double)crow[col] - ui0 - v[q];
                        if (cur < minv[q]) { minv[q] = cur; way_sh[col + 1] = j0; }
                        if (minv[q] < bval) { bval = minv[q]; bj = col + 1; }
                    }
                }
                // exact fp64 argmin across warp (ordered-u64 butterfly, lowest j ties)
                unsigned long long key = order_f64(bval);
                #pragma unroll
                for (int off = 16; off; off >>= 1) {
                    unsigned long long ok = __shfl_xor_sync(FULL, key, off);
                    int oj = __shfl_xor_sync(FULL, bj, off);
                    if (ok < key || (ok == key && oj < bj)) { key = ok; bj = oj; }
                }
                double delta = unorder_f64(key);
                j0 = bj;
                #pragma unroll
                for (int q = 0; q < QMAX; q++) {
                    int col = lane + 32 * q;
                    if (col < N) {
                        if (usedmask & (1u << q)) {
                            u_sh[p_sh[col + 1]] += delta;
                            v[q] -= delta;
                        } else {
                            minv[q] -= delta;
                        }
                    }
                }
                if (lane == 0) u_sh[p_sh[0]] += delta;
                __syncwarp();
                if (p_sh[j0] == 0) break;
            }
            if (lane == 0) {
                int jj = j0;
                while (jj) {
                    int j1 = way_sh[jj];
                    p_sh[jj] = p_sh[j1];
                    jj = j1;
                }
            }
            __syncwarp();
        }
    }
    __syncthreads();

    // --- pair losses + obj_t scatter (all 128 threads) ---
    double bb = 0.0, gg = 0.0, ab = 0.0, ag = 0.0;
    #pragma unroll
    for (int q = 0; q < 3; q++) {
        int col = tid + 128 * q;
        if (col < N) {
            int r = p_sh[col + 1];
            if (r > 0) {
                int tj = vid_sh[r - 1];
                float4 p = pred[b * N + col];
                float4 t = tgt[b * M + tj];
                bb += (double)l1_cxcywh(p, t);
                gg += (double)(1.0f - giou_cxcywh(p, t));
                g_obj_t[b * N + col] = 1.0f;
                for (int l = 0; l < L; l++) {
                    float4 a = aux_pred[((size_t)l * B + b) * N + col];
                    ab += (double)l1_cxcywh(a, t);
                    ag += (double)(1.0f - giou_cxcywh(a, t));
                }
            }
        }
    }
    #pragma unroll
    for (int off = 16; off; off >>= 1) {
        bb += __shfl_xor_sync(FULL, bb, off);
        gg += __shfl_xor_sync(FULL, gg, off);
        ab += __shfl_xor_sync(FULL, ab, off);
        ag += __shfl_xor_sync(FULL, ag, off);
    }
    if (lane == 0) {
        s_red[wid] = bb; s_red[4 + wid] = gg;
        s_red[8 + wid] = ab; s_red[12 + wid] = ag;
    }
    __syncthreads();
    if (tid == 0) {
        g_pair[b * 4 + 0] = s_red[0] + s_red[1] + s_red[2] + s_red[3];
        g_pair[b * 4 + 1] = s_red[4] + s_red[5] + s_red[6] + s_red[7];
        g_pair[b * 4 + 2] = s_red[8] + s_red[9] + s_red[10] + s_red[11];
        g_pair[b * 4 + 3] = s_red[12] + s_red[13] + s_red[14] + s_red[15];
    }
}

// ---------------- K3: BCE sums + last-block final reduction ----------------
__global__ void bce_final_kernel(const float* __restrict__ obj,
                                 const float* __restrict__ aux_obj,
                                 float* __restrict__ out,
                                 int B, int N, int L, int nblocks)
{
    int tid = threadIdx.x;
    int bid = blockIdx.x;
    int idx = bid * 256 + tid;
    int mt = B * N;
    int total = mt * (1 + L);
    double vm = 0.0, va = 0.0;
    if (idx < total) {
        if (idx < mt) {
            vm = (double)bce_f(obj[idx], g_obj_t[idx]);
        } else {
            int a = idx - mt;
            va = (double)bce_f(aux_obj[a], g_obj_t[a % mt]);
        }
    }
    __shared__ double rm[256];
    __shared__ double ra[256];
    __shared__ int s_last;
    rm[tid] = vm;
    ra[tid] = va;
    __syncthreads();
    for (int off = 128; off; off >>= 1) {
        if (tid < off) { rm[tid] += rm[tid + off]; ra[tid] += ra[tid + off]; }
        __syncthreads();
    }
    if (tid == 0) {
        g_bce[2 * bid + 0] = rm[0];
        g_bce[2 * bid + 1] = ra[0];
        __threadfence();
        unsigned t = atomicAdd(&g_sem, 1u);
        s_last = (t == (unsigned)(nblocks - 1)) ? 1 : 0;
    }
    __syncthreads();
    if (!s_last) return;
    __threadfence();

    double om = 0.0, oa = 0.0;
    for (int i = tid; i < nblocks; i += 256) {
        om += g_bce[2 * i + 0];
        oa += g_bce[2 * i + 1];
    }
    rm[tid] = om;
    ra[tid] = oa;
    __syncthreads();
    for (int off = 128; off; off >>= 1) {
        if (tid < off) { rm[tid] += rm[tid + off]; ra[tid] += ra[tid + off]; }
        __syncthreads();
    }
    if (tid == 0) {
        double objs = rm[0], aobj = ra[0];
        double nb = 0.0, cls = 0.0, bbox = 0.0, gi = 0.0, abx = 0.0, agx = 0.0;
        for (int bi = 0; bi < B; bi++) {
            nb += (double)g_k[bi];
            cls += g_cls[bi];
            bbox += g_pair[bi * 4 + 0];
            gi   += g_pair[bi * 4 + 1];
            abx  += g_pair[bi * 4 + 2];
            agx  += g_pair[bi * 4 + 3];
        }
        if (nb < 1.0) nb = 1.0;
        double BN = (double)B * (double)N;
        double tot = cls / (double)B
                   + 5.0 * bbox / nb
                   + 2.0 * gi / nb
                   + objs / BN
                   + (5.0 * abx / nb + 2.0 * agx / nb + aobj / BN) * 0.5 / (double)L;
        out[0] = (float)tot;
    }
}

// ---------------- launch ----------------
extern "C" void kernel_launch(void* const* d_in, const int* in_sizes, int n_in,
                              void* d_out, int out_size)
{
    const float* cls      = (const float*)d_in[0];
    const int*   label    = (const int*)d_in[1];
    const float* pred     = (const float*)d_in[2];
    const float* obj      = (const float*)d_in[3];
    const float* tgt      = (const float*)d_in[4];
    const float* mask     = (const float*)d_in[5];
    const float* aux_pred = (const float*)d_in[6];
    const float* aux_obj  = (const float*)d_in[7];

    int B = in_sizes[1];
    int C = in_sizes[0] / B;
    int N = in_sizes[3] / B;
    int M = in_sizes[5] / B;
    int L = in_sizes[6] / (B * N * 4);
    float* out = (float*)d_out;

    int cost_blocks = (B * M * N + 255) / 256;
    prep_kernel<<<cost_blocks + B, 256>>>((const float4*)pred, (const float4*)tgt,
                                          cls, label, B, N, M, C, cost_blocks);
    hungarian_kernel<<<B, 128>>>(mask, (const float4*)pred, (const float4*)tgt,
                                 (const float4*)aux_pred, B, N, M, L);
    int nbce = (B * N * (1 + L) + 255) / 256;
    bce_final_kernel<<<nbce, 256>>>(obj, aux_obj, out, B, N, L, nbce);
}

// round 3
// speedup vs baseline: 2.4284x; 2.4284x over previous
#include <cuda_runtime.h>
#include <math.h>
#include <float.h>

// Problem capacities (B=32, N=300, M=60, L=5, C=1000)
#define CAP_B 32
#define CAP_N 300
#define CAP_M 60
#define QMAX 10            // ceil(300/32) columns per lane
#define BCE_CAP_BLOCKS 512

// ---------------- device scratch (no allocations allowed) ----------------
__device__ float    g_cost[CAP_B * CAP_M * CAP_N];  // [b][t][j]
__device__ int      g_k[CAP_B];
__device__ float    g_obj_t[CAP_B * CAP_N];
__device__ double   g_cls[CAP_B];
__device__ double   g_pair[CAP_B * 4];              // {bbox, giou, aux_bbox, aux_giou}
__device__ double   g_bce[BCE_CAP_BLOCKS * 2];
__device__ unsigned g_sem;

// ---------------- helpers ----------------
__device__ __forceinline__ float giou_f(
    float ax0, float ay0, float ax1, float ay1,
    float bx0, float by0, float bx1, float by1)
{
    const float EPS = 1e-7f;
    float area_a = (ax1 - ax0) * (ay1 - ay0);
    float area_b = (bx1 - bx0) * (by1 - by0);
    float ltx = fmaxf(ax0, bx0), lty = fmaxf(ay0, by0);
    float rbx = fminf(ax1, bx1), rby = fminf(ay1, by1);
    float wx = fmaxf(rbx - ltx, 0.0f), wy = fmaxf(rby - lty, 0.0f);
    float inter = wx * wy;
    float uni = area_a + area_b - inter;
    float iou = inter / (uni + EPS);
    float ex = fmaxf(fmaxf(ax1, bx1) - fminf(ax0, bx0), 0.0f);
    float ey = fmaxf(fmaxf(ay1, by1) - fminf(ay0, by0), 0.0f);
    float enc = ex * ey;
    return iou - (enc - uni) / (enc + EPS);
}

__device__ __forceinline__ float giou_cxcywh(float4 p, float4 q)
{
    return giou_f(p.x - p.z * 0.5f, p.y - p.w * 0.5f, p.x + p.z * 0.5f, p.y + p.w * 0.5f,
                  q.x - q.z * 0.5f, q.y - q.w * 0.5f, q.x + q.z * 0.5f, q.y + q.w * 0.5f);
}

__device__ __forceinline__ float l1_cxcywh(float4 p, float4 q)
{
    return fabsf(p.x - q.x) + fabsf(p.y - q.y) + fabsf(p.z - q.z) + fabsf(p.w - q.w);
}

__device__ __forceinline__ float bce_f(float x, float t)
{
    return fmaxf(x, 0.0f) - x * t + log1pf(expf(-fabsf(x)));
}

// ordered mapping (ascending) for f32
__device__ __forceinline__ unsigned order_f32(float f)
{
    unsigned u = __float_as_uint(f);
    return (u & 0x80000000u) ? ~u : (u | 0x80000000u);
}
__device__ __forceinline__ float unorder_f32(unsigned k)
{
    unsigned u = (k & 0x80000000u) ? (k & 0x7fffffffu) : ~k;
    return __uint_as_float(u);
}

// pack (value, col) so u64-min gives min value, ties -> lowest col
__device__ __forceinline__ unsigned long long pack_vc(float v, unsigned col)
{
    return ((unsigned long long)order_f32(v) << 32) | (unsigned long long)col;
}

__device__ __forceinline__ unsigned long long warp_min_u64(unsigned long long x)
{
    const unsigned FULL = 0xffffffffu;
    #pragma unroll
    for (int off = 16; off; off >>= 1) {
        unsigned long long o = __shfl_xor_sync(FULL, x, off);
        x = (o < x) ? o : x;
    }
    return x;
}

// ---------------- K1: cost matrix + cls loss + init ----------------
__global__ void prep_kernel(const float4* __restrict__ pred,
                            const float4* __restrict__ tgt,
                            const float* __restrict__ cls,
                            const int* __restrict__ label,
                            int B, int N, int M, int C, int cost_blocks)
{
    __shared__ float sred[256];
    if ((int)blockIdx.x < cost_blocks) {
        int idx = blockIdx.x * 256 + threadIdx.x;
        if (idx == 0) g_sem = 0u;
        if (idx < B * N) g_obj_t[idx] = 0.0f;
        int total = B * M * N;
        if (idx < total) {
            int j = idx % N;
            int t = (idx / N) % M;
            int b = idx / (N * M);
            float4 p = pred[b * N + j];
            float4 q = tgt[b * M + t];
            g_cost[idx] = 5.0f * l1_cxcywh(p, q) - 2.0f * giou_cxcywh(p, q);
        }
    } else {
        int b = blockIdx.x - cost_blocks;
        int tid = threadIdx.x;
        const float* x = cls + (size_t)b * C;
        float m = -FLT_MAX;
        for (int c = tid; c < C; c += 256) m = fmaxf(m, x[c]);
        sred[tid] = m;
        __syncthreads();
        for (int off = 128; off; off >>= 1) {
            if (tid < off) sred[tid] = fmaxf(sred[tid], sred[tid + off]);
            __syncthreads();
        }
        m = sred[0];
        __syncthreads();
        float s = 0.0f;
        for (int c = tid; c < C; c += 256) s += expf(x[c] - m);
        sred[tid] = s;
        __syncthreads();
        for (int off = 128; off; off >>= 1) {
            if (tid < off) sred[tid] += sred[tid + off];
            __syncthreads();
        }
        if (tid == 0) g_cls[b] = (double)(m + logf(sred[0]) - x[label[b]]);
    }
}

// ---------------- K2: LAPJV fp32 (greedy init + sparse augmentation) + pair losses ----
// One block of 128 threads per batch. Greedy row-minima on 4 warps; the few
// Dijkstra augmentations run warp-synchronous on warp 0 in fp32 (lat-4 pipes).
__global__ void __launch_bounds__(128, 1)
hungarian_kernel(const float* __restrict__ mask,
                 const float4* __restrict__ pred,
                 const float4* __restrict__ tgt,
                 const float4* __restrict__ aux_pred,
                 int B, int N, int M, int L)
{
    const unsigned FULL = 0xffffffffu;
    int b = blockIdx.x;
    int tid = threadIdx.x;
    int lane = tid & 31, wid = tid >> 5;

    __shared__ float u_sh[CAP_M + 2];
    __shared__ int p_sh[CAP_N + 1];       // column j (1..N) -> row (1-based), 0 = free
    __shared__ int way_sh[CAP_N + 1];
    __shared__ int vid_sh[CAP_M];
    __shared__ int gcol_sh[CAP_M];        // greedy argmin column per row
    __shared__ int rowcol_sh[CAP_M];      // resolved greedy col or -1
    __shared__ int s_k;
    __shared__ double s_red[16];

    for (int j = tid; j <= N; j += 128) { p_sh[j] = 0; way_sh[j] = 0; }
    for (int r = tid; r <= M; r += 128) u_sh[r] = 0.0f;

    const float* mrow = mask + (size_t)b * M;
    if (wid == 0) {
        bool v0 = (lane < M) && (mrow[lane] > 0.5f);
        bool v1 = (32 + lane < M) && (mrow[32 + lane] > 0.5f);
        unsigned b0 = __ballot_sync(FULL, v0);
        unsigned b1 = __ballot_sync(FULL, v1);
        unsigned lm = (1u << lane) - 1u;
        if (v0) vid_sh[__popc(b0 & lm)] = lane;
        if (v1) vid_sh[__popc(b0) + __popc(b1 & lm)] = 32 + lane;
        if (lane == 0) {
            s_k = __popc(b0) + __popc(b1);
            g_k[b] = s_k;
        }
    }
    __syncthreads();
    int k = s_k;
    const float* cb = g_cost + (size_t)b * M * N;

    // --- greedy phase: row minima + argmin columns (rows striped over 4 warps) ---
    for (int i = wid; i < k; i += 4) {
        const float* crow = cb + (size_t)vid_sh[i] * N;
        unsigned long long best = 0xFFFFFFFFFFFFFFFFull;
        #pragma unroll
        for (int q = 0; q < QMAX; q++) {
            int col = lane + 32 * q;
            if (col < N) {
                unsigned long long cand = pack_vc(crow[col], (unsigned)col);
                if (cand < best) best = cand;
            }
        }
        best = warp_min_u64(best);
        if (lane == 0) {
            u_sh[i + 1] = unorder_f32((unsigned)(best >> 32));
            gcol_sh[i] = (int)(best & 0xFFFFFFFFull);
        }
    }
    __syncthreads();

    // serial deterministic conflict resolution
    if (tid == 0) {
        for (int i = 0; i < k; i++) {
            int c = gcol_sh[i];
            if (p_sh[c + 1] == 0) { p_sh[c + 1] = i + 1; rowcol_sh[i] = c; }
            else rowcol_sh[i] = -1;
        }
    }
    __syncthreads();

    // --- Dijkstra augmentation for unassigned rows (warp 0, fp32) ---
    if (wid == 0) {
        float v[QMAX];
        #pragma unroll
        for (int q = 0; q < QMAX; q++) v[q] = 0.0f;

        for (int i = 0; i < k; i++) {
            if (rowcol_sh[i] >= 0) continue;
            float minv[QMAX];
            #pragma unroll
            for (int q = 0; q < QMAX; q++) minv[q] = INFINITY;
            unsigned usedmask = 0;
            if (lane == 0) p_sh[0] = i + 1;
            __syncwarp();
            int j0 = 0;
            while (true) {
                if (j0 > 0 && ((j0 - 1) & 31) == lane)
                    usedmask |= 1u << ((j0 - 1) >> 5);
                int i0 = p_sh[j0];
                float ui0 = u_sh[i0];
                const float* crow = cb + (size_t)vid_sh[i0 - 1] * N;
                unsigned long long best = 0xFFFFFFFFFFFFFFFFull;
                #pragma unroll
                for (int q = 0; q < QMAX; q++) {
                    int col = lane + 32 * q;
                    if (col < N && !(usedmask & (1u << q))) {
                        float cur = crow[col] - ui0 - v[q];
                        if (cur < minv[q]) { minv[q] = cur; way_sh[col + 1] = j0; }
                        unsigned long long cand = pack_vc(minv[q], (unsigned)(col + 1));
                        if (cand < best) best = cand;
                    }
                }
                best = warp_min_u64(best);
                float delta = unorder_f32((unsigned)(best >> 32));
                j0 = (int)(best & 0xFFFFFFFFull);
                #pragma unroll
                for (int q = 0; q < QMAX; q++) {
                    int col = lane + 32 * q;
                    if (col < N) {
                        if (usedmask & (1u << q)) {
                            u_sh[p_sh[col + 1]] += delta;
                            v[q] -= delta;
                        } else {
                            minv[q] -= delta;
                        }
                    }
                }
                if (lane == 0) u_sh[p_sh[0]] += delta;
                __syncwarp();
                if (p_sh[j0] == 0) break;
            }
            if (lane == 0) {
                int jj = j0;
                while (jj) {
                    int j1 = way_sh[jj];
                    p_sh[jj] = p_sh[j1];
                    jj = j1;
                }
            }
            __syncwarp();
        }
    }
    __syncthreads();

    // --- pair losses + obj_t scatter (all 128 threads) ---
    double bb = 0.0, gg = 0.0, ab = 0.0, ag = 0.0;
    #pragma unroll
    for (int q = 0; q < 3; q++) {
        int col = tid + 128 * q;
        if (col < N) {
            int r = p_sh[col + 1];
            if (r > 0) {
                int tj = vid_sh[r - 1];
                float4 p = pred[b * N + col];
                float4 t = tgt[b * M + tj];
                bb += (double)l1_cxcywh(p, t);
                gg += (double)(1.0f - giou_cxcywh(p, t));
                g_obj_t[b * N + col] = 1.0f;
                for (int l = 0; l < L; l++) {
                    float4 a = aux_pred[((size_t)l * B + b) * N + col];
                    ab += (double)l1_cxcywh(a, t);
                    ag += (double)(1.0f - giou_cxcywh(a, t));
                }
            }
        }
    }
    #pragma unroll
    for (int off = 16; off; off >>= 1) {
        bb += __shfl_xor_sync(FULL, bb, off);
        gg += __shfl_xor_sync(FULL, gg, off);
        ab += __shfl_xor_sync(FULL, ab, off);
        ag += __shfl_xor_sync(FULL, ag, off);
    }
    if (lane == 0) {
        s_red[wid] = bb; s_red[4 + wid] = gg;
        s_red[8 + wid] = ab; s_red[12 + wid] = ag;
    }
    __syncthreads();
    if (tid == 0) {
        g_pair[b * 4 + 0] = s_red[0] + s_red[1] + s_red[2] + s_red[3];
        g_pair[b * 4 + 1] = s_red[4] + s_red[5] + s_red[6] + s_red[7];
        g_pair[b * 4 + 2] = s_red[8] + s_red[9] + s_red[10] + s_red[11];
        g_pair[b * 4 + 3] = s_red[12] + s_red[13] + s_red[14] + s_red[15];
    }
}

// ---------------- K3: BCE sums + last-block final reduction ----------------
__global__ void bce_final_kernel(const float* __restrict__ obj,
                                 const float* __restrict__ aux_obj,
                                 float* __restrict__ out,
                                 int B, int N, int L, int nblocks)
{
    int tid = threadIdx.x;
    int bid = blockIdx.x;
    int idx = bid * 256 + tid;
    int mt = B * N;
    int total = mt * (1 + L);
    double vm = 0.0, va = 0.0;
    if (idx < total) {
        if (idx < mt) {
            vm = (double)bce_f(obj[idx], g_obj_t[idx]);
        } else {
            int a = idx - mt;
            va = (double)bce_f(aux_obj[a], g_obj_t[a % mt]);
        }
    }
    __shared__ double rm[256];
    __shared__ double ra[256];
    __shared__ int s_last;
    rm[tid] = vm;
    ra[tid] = va;
    __syncthreads();
    for (int off = 128; off; off >>= 1) {
        if (tid < off) { rm[tid] += rm[tid + off]; ra[tid] += ra[tid + off]; }
        __syncthreads();
    }
    if (tid == 0) {
        g_bce[2 * bid + 0] = rm[0];
        g_bce[2 * bid + 1] = ra[0];
        __threadfence();
        unsigned t = atomicAdd(&g_sem, 1u);
        s_last = (t == (unsigned)(nblocks - 1)) ? 1 : 0;
    }
    __syncthreads();
    if (!s_last) return;
    __threadfence();

    double om = 0.0, oa = 0.0;
    for (int i = tid; i < nblocks; i += 256) {
        om += g_bce[2 * i + 0];
        oa += g_bce[2 * i + 1];
    }
    rm[tid] = om;
    ra[tid] = oa;
    __syncthreads();
    for (int off = 128; off; off >>= 1) {
        if (tid < off) { rm[tid] += rm[tid + off]; ra[tid] += ra[tid + off]; }
        __syncthreads();
    }
    if (tid == 0) {
        double objs = rm[0], aobj = ra[0];
        double nb = 0.0, cls = 0.0, bbox = 0.0, gi = 0.0, abx = 0.0, agx = 0.0;
        for (int bi = 0; bi < B; bi++) {
            nb += (double)g_k[bi];
            cls += g_cls[bi];
            bbox += g_pair[bi * 4 + 0];
            gi   += g_pair[bi * 4 + 1];
            abx  += g_pair[bi * 4 + 2];
            agx  += g_pair[bi * 4 + 3];
        }
        if (nb < 1.0) nb = 1.0;
        double BN = (double)B * (double)N;
        double tot = cls / (double)B
                   + 5.0 * bbox / nb
                   + 2.0 * gi / nb
                   + objs / BN
                   + (5.0 * abx / nb + 2.0 * agx / nb + aobj / BN) * 0.5 / (double)L;
        out[0] = (float)tot;
    }
}

// ---------------- launch ----------------
extern "C" void kernel_launch(void* const* d_in, const int* in_sizes, int n_in,
                              void* d_out, int out_size)
{
    const float* cls      = (const float*)d_in[0];
    const int*   label    = (const int*)d_in[1];
    const float* pred     = (const float*)d_in[2];
    const float* obj      = (const float*)d_in[3];
    const float* tgt      = (const float*)d_in[4];
    const float* mask     = (const float*)d_in[5];
    const float* aux_pred = (const float*)d_in[6];
    const float* aux_obj  = (const float*)d_in[7];

    int B = in_sizes[1];
    int C = in_sizes[0] / B;
    int N = in_sizes[3] / B;
    int M = in_sizes[5] / B;
    int L = in_sizes[6] / (B * N * 4);
    float* out = (float*)d_out;

    int cost_blocks = (B * M * N + 255) / 256;
    prep_kernel<<<cost_blocks + B, 256>>>((const float4*)pred, (const float4*)tgt,
                                          cls, label, B, N, M, C, cost_blocks);
    hungarian_kernel<<<B, 128>>>(mask, (const float4*)pred, (const float4*)tgt,
                                 (const float4*)aux_pred, B, N, M, L);
    int nbce = (B * N * (1 + L) + 255) / 256;
    bce_final_kernel<<<nbce, 256>>>(obj, aux_obj, out, B, N, L, nbce);
}

// round 4
// speedup vs baseline: 3.4991x; 1.4409x over previous
#include <cuda_runtime.h>
#include <math.h>
#include <float.h>

// Problem capacities (B=32, N=300, M=60, L=5, C=1000)
#define CAP_B 32
#define CAP_N 300
#define CAP_M 60
#define QMAX 10            // ceil(300/32) columns per lane
#define BCE_CAP_BLOCKS 512
#define QUEUE_CAP 256

// ---------------- device scratch (no allocations allowed) ----------------
__device__ int      g_k[CAP_B];
__device__ float    g_obj_t[CAP_B * CAP_N];
__device__ double   g_cls[CAP_B];
__device__ double   g_pair[CAP_B * 4];              // {bbox, giou, aux_bbox, aux_giou}
__device__ double   g_bce[BCE_CAP_BLOCKS * 2];
__device__ unsigned g_sem;                          // zero-init; reset at end of each run

// ---------------- helpers ----------------
__device__ __forceinline__ float giou_f(
    float ax0, float ay0, float ax1, float ay1,
    float bx0, float by0, float bx1, float by1)
{
    const float EPS = 1e-7f;
    float area_a = (ax1 - ax0) * (ay1 - ay0);
    float area_b = (bx1 - bx0) * (by1 - by0);
    float ltx = fmaxf(ax0, bx0), lty = fmaxf(ay0, by0);
    float rbx = fminf(ax1, bx1), rby = fminf(ay1, by1);
    float wx = fmaxf(rbx - ltx, 0.0f), wy = fmaxf(rby - lty, 0.0f);
    float inter = wx * wy;
    float uni = area_a + area_b - inter;
    float iou = inter / (uni + EPS);
    float ex = fmaxf(fmaxf(ax1, bx1) - fminf(ax0, bx0), 0.0f);
    float ey = fmaxf(fmaxf(ay1, by1) - fminf(ay0, by0), 0.0f);
    float enc = ex * ey;
    return iou - (enc - uni) / (enc + EPS);
}

__device__ __forceinline__ float giou_cxcywh(float4 p, float4 q)
{
    return giou_f(p.x - p.z * 0.5f, p.y - p.w * 0.5f, p.x + p.z * 0.5f, p.y + p.w * 0.5f,
                  q.x - q.z * 0.5f, q.y - q.w * 0.5f, q.x + q.z * 0.5f, q.y + q.w * 0.5f);
}

__device__ __forceinline__ float l1_cxcywh(float4 p, float4 q)
{
    return fabsf(p.x - q.x) + fabsf(p.y - q.y) + fabsf(p.z - q.z) + fabsf(p.w - q.w);
}

__device__ __forceinline__ float bce_f(float x, float t)
{
    return fmaxf(x, 0.0f) - x * t + log1pf(expf(-fabsf(x)));
}

// ordered mapping (ascending) for f32
__device__ __forceinline__ unsigned order_f32(float f)
{
    unsigned u = __float_as_uint(f);
    return (u & 0x80000000u) ? ~u : (u | 0x80000000u);
}
__device__ __forceinline__ float unorder_f32(unsigned k)
{
    unsigned u = (k & 0x80000000u) ? (k & 0x7fffffffu) : ~k;
    return __uint_as_float(u);
}
__device__ __forceinline__ unsigned long long pack_vc(float v, unsigned col)
{
    return ((unsigned long long)order_f32(v) << 32) | (unsigned long long)col;
}

// ---------------- K1: LAPJV (greedy + ARR + sparse Dijkstra) + pair losses --------
// One block of 128 threads per batch. Cost matrix built in shared memory.
__global__ void __launch_bounds__(128, 1)
hungarian_kernel(const float* __restrict__ mask,
                 const float4* __restrict__ pred,
                 const float4* __restrict__ tgt,
                 const float4* __restrict__ aux_pred,
                 int B, int N, int M, int L)
{
    extern __shared__ float cost_sh[];               // [k][N] row-major (CAP_M*CAP_N)
    const unsigned FULL = 0xffffffffu;
    int b = blockIdx.x;
    int tid = threadIdx.x;
    int lane = tid & 31, wid = tid >> 5;

    __shared__ float4 pred_sh[CAP_N];
    __shared__ float4 tgt_sh[CAP_M];
    __shared__ float u_sh[CAP_M + 2];
    __shared__ int p_sh[CAP_N + 1];     // column j (1..N) -> row (1-based), 0 = free
    __shared__ int way_sh[CAP_N + 1];
    __shared__ int vid_sh[CAP_M];
    __shared__ int gcol_sh[CAP_M];      // greedy argmin column per row
    __shared__ int queue_sh[QUEUE_CAP]; // unassigned-row worklist
    __shared__ int s_k, s_nfree;
    __shared__ double s_red[16];

    for (int j = tid; j <= N; j += 128) p_sh[j] = 0;
    for (int j = tid; j < N; j += 128) pred_sh[j] = pred[b * N + j];
    for (int t = tid; t < M; t += 128) tgt_sh[t] = tgt[b * M + t];
    if (tid <= M) u_sh[tid] = 0.0f;

    const float* mrow = mask + (size_t)b * M;
    if (wid == 0) {
        bool v0 = (lane < M) && (mrow[lane] > 0.5f);
        bool v1 = (32 + lane < M) && (mrow[32 + lane] > 0.5f);
        unsigned b0 = __ballot_sync(FULL, v0);
        unsigned b1 = __ballot_sync(FULL, v1);
        unsigned lm = (1u << lane) - 1u;
        if (v0) vid_sh[__popc(b0 & lm)] = lane;
        if (v1) vid_sh[__popc(b0) + __popc(b1 & lm)] = 32 + lane;
        if (lane == 0) {
            s_k = __popc(b0) + __popc(b1);
            g_k[b] = s_k;
        }
    }
    __syncthreads();
    int k = s_k;

    // --- build cost matrix in smem: cost[i][j] = 5*L1 - 2*GIoU ---
    for (int idx = tid; idx < k * N; idx += 128) {
        int i = idx / N;
        int j = idx - i * N;
        float4 p = pred_sh[j];
        float4 q = tgt_sh[vid_sh[i]];
        cost_sh[idx] = 5.0f * l1_cxcywh(p, q) - 2.0f * giou_cxcywh(p, q);
    }
    __syncthreads();

    // --- greedy: per-row min + argmin (rows striped over 4 warps) ---
    for (int i = wid; i < k; i += 4) {
        const float* crow = cost_sh + i * N;
        unsigned long long best = 0xFFFFFFFFFFFFFFFFull;
        #pragma unroll
        for (int q = 0; q < QMAX; q++) {
            int col = lane + 32 * q;
            if (col < N) {
                unsigned long long cand = pack_vc(crow[col], (unsigned)col);
                if (cand < best) best = cand;
            }
        }
        #pragma unroll
        for (int off = 16; off; off >>= 1) {
            unsigned long long o = __shfl_xor_sync(FULL, best, off);
            if (o < best) best = o;
        }
        if (lane == 0) {
            u_sh[i + 1] = unorder_f32((unsigned)(best >> 32));
            gcol_sh[i] = (int)(best & 0xFFFFFFFFull);
        }
    }
    __syncthreads();

    // --- conflict resolution (serial, deterministic) -> free-row queue ---
    if (tid == 0) {
        int nf = 0;
        for (int i = 0; i < k; i++) {
            int c = gcol_sh[i];
            if (p_sh[c + 1] == 0) p_sh[c + 1] = i + 1;
            else queue_sh[nf++] = i;
        }
        s_nfree = nf;
    }
    __syncthreads();

    // --- warp 0: ARR + Dijkstra (duals v live in warp-0 registers) ---
    if (wid == 0) {
        float v[QMAX];
        #pragma unroll
        for (int q = 0; q < QMAX; q++) v[q] = 0.0f;

        int qh = 0, qt = s_nfree;
        // Phase ARR: Jonker-Volgenant augmenting row reduction
        int cap = 2 * k + 8;
        int processed = 0;
        while (qh < qt && processed < cap) {
            processed++;
            __syncwarp();
            int i = queue_sh[qh++];
            const float* crow = cost_sh + i * N;
            unsigned long long b1 = 0xFFFFFFFFFFFFFFFFull;
            unsigned long long b2 = 0xFFFFFFFFFFFFFFFFull;
            #pragma unroll
            for (int q = 0; q < QMAX; q++) {
                int col = lane + 32 * q;
                if (col < N) {
                    unsigned long long pk = pack_vc(crow[col] - v[q], (unsigned)col);
                    if (pk < b1) { b2 = b1; b1 = pk; }
                    else if (pk < b2) b2 = pk;
                }
            }
            #pragma unroll
            for (int off = 16; off; off >>= 1) {
                unsigned long long o1 = __shfl_xor_sync(FULL, b1, off);
                unsigned long long o2 = __shfl_xor_sync(FULL, b2, off);
                unsigned long long hi = (b1 < o1) ? o1 : b1;
                b1 = (b1 < o1) ? b1 : o1;
                unsigned long long lo2 = (b2 < o2) ? b2 : o2;
                b2 = (hi < lo2) ? hi : lo2;
            }
            int j1 = (int)(b1 & 0xFFFFFFFFull);
            int j2 = (int)(b2 & 0xFFFFFFFFull);
            float u1 = unorder_f32((unsigned)(b1 >> 32));
            float u2 = unorder_f32((unsigned)(b2 >> 32));
            bool strict = ((unsigned)(b1 >> 32)) != ((unsigned)(b2 >> 32));

            int i1 = 0;
            if (lane == 0) i1 = p_sh[j1 + 1];
            i1 = __shfl_sync(FULL, i1, 0);
            if (strict) {
                if ((j1 & 31) == lane) v[j1 >> 5] -= (u2 - u1);
            } else if (i1 != 0) {
                j1 = j2;
                if (lane == 0) i1 = p_sh[j2 + 1];
                i1 = __shfl_sync(FULL, i1, 0);
            }
            if (lane == 0) {
                u_sh[i + 1] = u2;
                p_sh[j1 + 1] = i + 1;
                if (i1 != 0 && qt < QUEUE_CAP) queue_sh[qt] = i1 - 1;
            }
            if (i1 != 0 && qt < QUEUE_CAP) qt++;
        }

        // Phase Dijkstra: full augmentation for any remaining free rows
        for (int qi = qh; qi < qt; qi++) {
            __syncwarp();
            int rfree = queue_sh[qi];
            float minv[QMAX];
            #pragma unroll
            for (int q = 0; q < QMAX; q++) minv[q] = INFINITY;
            unsigned usedmask = 0;
            if (lane == 0) p_sh[0] = rfree + 1;
            __syncwarp();
            int j0 = 0;
            while (true) {
                if (j0 > 0 && ((j0 - 1) & 31) == lane)
                    usedmask |= 1u << ((j0 - 1) >> 5);
                int i0 = p_sh[j0];
                float ui0 = u_sh[i0];
                const float* crow = cost_sh + (i0 - 1) * N;
                float bval = INFINITY;
                int bj = 0x7FFFFFFF;
                #pragma unroll
                for (int q = 0; q < QMAX; q++) {
                    int col = lane + 32 * q;
                    if (col < N && !(usedmask & (1u << q))) {
                        float cur = crow[col] - ui0 - v[q];
                        if (cur < minv[q]) { minv[q] = cur; way_sh[col + 1] = j0; }
                        if (minv[q] < bval) { bval = minv[q]; bj = col + 1; }
                    }
                }
                unsigned vkey = order_f32(bval);
                unsigned vmin = __reduce_min_sync(FULL, vkey);
                unsigned ckey = (vkey == vmin) ? (unsigned)bj : 0x7FFFFFFFu;
                unsigned cmin = __reduce_min_sync(FULL, ckey);
                float delta = unorder_f32(vmin);
                j0 = (int)cmin;
                #pragma unroll
                for (int q = 0; q < QMAX; q++) {
                    int col = lane + 32 * q;
                    if (col < N) {
                        if (usedmask & (1u << q)) {
                            u_sh[p_sh[col + 1]] += delta;
                            v[q] -= delta;
                        } else {
                            minv[q] -= delta;
                        }
                    }
                }
                if (lane == 0) u_sh[p_sh[0]] += delta;
                __syncwarp();
                if (p_sh[j0] == 0) break;
            }
            if (lane == 0) {
                int jj = j0;
                while (jj) {
                    int j1a = way_sh[jj];
                    p_sh[jj] = p_sh[j1a];
                    jj = j1a;
                }
            }
        }
    }
    __syncthreads();

    // --- pair losses + obj_t (covers init: writes all N columns) ---
    double bb = 0.0, gg = 0.0, ab = 0.0, ag = 0.0;
    #pragma unroll
    for (int q = 0; q < 3; q++) {
        int col = tid + 128 * q;
        if (col < N) {
            int r = p_sh[col + 1];
            g_obj_t[b * N + col] = (r > 0) ? 1.0f : 0.0f;
            if (r > 0) {
                float4 p = pred_sh[col];
                float4 t = tgt_sh[vid_sh[r - 1]];
                bb += (double)l1_cxcywh(p, t);
                gg += (double)(1.0f - giou_cxcywh(p, t));
                for (int l = 0; l < L; l++) {
                    float4 a = aux_pred[((size_t)l * B + b) * N + col];
                    ab += (double)l1_cxcywh(a, t);
                    ag += (double)(1.0f - giou_cxcywh(a, t));
                }
            }
        }
    }
    #pragma unroll
    for (int off = 16; off; off >>= 1) {
        bb += __shfl_xor_sync(FULL, bb, off);
        gg += __shfl_xor_sync(FULL, gg, off);
        ab += __shfl_xor_sync(FULL, ab, off);
        ag += __shfl_xor_sync(FULL, ag, off);
    }
    if (lane == 0) {
        s_red[wid] = bb; s_red[4 + wid] = gg;
        s_red[8 + wid] = ab; s_red[12 + wid] = ag;
    }
    __syncthreads();
    if (tid == 0) {
        g_pair[b * 4 + 0] = s_red[0] + s_red[1] + s_red[2] + s_red[3];
        g_pair[b * 4 + 1] = s_red[4] + s_red[5] + s_red[6] + s_red[7];
        g_pair[b * 4 + 2] = s_red[8] + s_red[9] + s_red[10] + s_red[11];
        g_pair[b * 4 + 3] = s_red[12] + s_red[13] + s_red[14] + s_red[15];
    }
}

// ---------------- K2: BCE + cls log-softmax + last-block final reduction ----------
__global__ void bce_final_kernel(const float* __restrict__ obj,
                                 const float* __restrict__ aux_obj,
                                 const float* __restrict__ cls,
                                 const int* __restrict__ label,
                                 float* __restrict__ out,
                                 int B, int N, int L, int C,
                                 int nbce, int nblocks)
{
    int tid = threadIdx.x;
    int bid = blockIdx.x;
    __shared__ double rm[256];
    __shared__ double ra[256];
    __shared__ int s_last;

    if (bid >= nbce) {
        // cls log-softmax block for batch b
        int b = bid - nbce;
        __shared__ float sred[256];
        const float* x = cls + (size_t)b * C;
        float m = -FLT_MAX;
        for (int c = tid; c < C; c += 256) m = fmaxf(m, x[c]);
        sred[tid] = m;
        __syncthreads();
        for (int off = 128; off; off >>= 1) {
            if (tid < off) sred[tid] = fmaxf(sred[tid], sred[tid + off]);
            __syncthreads();
        }
        m = sred[0];
        __syncthreads();
        float s = 0.0f;
        for (int c = tid; c < C; c += 256) s += expf(x[c] - m);
        sred[tid] = s;
        __syncthreads();
        for (int off = 128; off; off >>= 1) {
            if (tid < off) sred[tid] += sred[tid + off];
            __syncthreads();
        }
        if (tid == 0) {
            g_cls[b] = (double)(m + logf(sred[0]) - x[label[b]]);
            __threadfence();
            atomicAdd(&g_sem, 1u);
        }
        return;  // cls blocks never do the final reduction (bce blocks outnumber them)
    }

    int idx = bid * 256 + tid;
    int mt = B * N;
    int total = mt * (1 + L);
    double vm = 0.0, va = 0.0;
    if (idx < total) {
        if (idx < mt) {
            vm = (double)bce_f(obj[idx], g_obj_t[idx]);
        } else {
            int a = idx - mt;
            va = (double)bce_f(aux_obj[a], g_obj_t[a % mt]);
        }
    }
    rm[tid] = vm;
    ra[tid] = va;
    __syncthreads();
    for (int off = 128; off; off >>= 1) {
        if (tid < off) { rm[tid] += rm[tid + off]; ra[tid] += ra[tid + off]; }
        __syncthreads();
    }
    if (tid == 0) {
        g_bce[2 * bid + 0] = rm[0];
        g_bce[2 * bid + 1] = ra[0];
        __threadfence();
        unsigned t = atomicAdd(&g_sem, 1u);
        s_last = (t == (unsigned)(nblocks - 1)) ? 1 : 0;
    }
    __syncthreads();
    if (!s_last) return;
    __threadfence();

    double om = 0.0, oa = 0.0;
    for (int i = tid; i < nbce; i += 256) {
        om += g_bce[2 * i + 0];
        oa += g_bce[2 * i + 1];
    }
    rm[tid] = om;
    ra[tid] = oa;
    __syncthreads();
    for (int off = 128; off; off >>= 1) {
        if (tid < off) { rm[tid] += rm[tid + off]; ra[tid] += ra[tid + off]; }
        __syncthreads();
    }
    if (tid == 0) {
        double objs = rm[0], aobj = ra[0];
        double nb = 0.0, clsl = 0.0, bbox = 0.0, gi = 0.0, abx = 0.0, agx = 0.0;
        for (int bi = 0; bi < B; bi++) {
            nb   += (double)g_k[bi];
            clsl += g_cls[bi];
            bbox += g_pair[bi * 4 + 0];
            gi   += g_pair[bi * 4 + 1];
            abx  += g_pair[bi * 4 + 2];
            agx  += g_pair[bi * 4 + 3];
        }
        if (nb < 1.0) nb = 1.0;
        double BN = (double)B * (double)N;
        double tot = clsl / (double)B
                   + 5.0 * bbox / nb
                   + 2.0 * gi / nb
                   + objs / BN
                   + (5.0 * abx / nb + 2.0 * agx / nb + aobj / BN) * 0.5 / (double)L;
        out[0] = (float)tot;
        g_sem = 0u;  // reset for next replay
    }
}

// ---------------- launch ----------------
extern "C" void kernel_launch(void* const* d_in, const int* in_sizes, int n_in,
                              void* d_out, int out_size)
{
    const float* cls      = (const float*)d_in[0];
    const int*   label    = (const int*)d_in[1];
    const float* pred     = (const float*)d_in[2];
    const float* obj      = (const float*)d_in[3];
    const float* tgt      = (const float*)d_in[4];
    const float* mask     = (const float*)d_in[5];
    const float* aux_pred = (const float*)d_in[6];
    const float* aux_obj  = (const float*)d_in[7];

    int B = in_sizes[1];
    int C = in_sizes[0] / B;
    int N = in_sizes[3] / B;
    int M = in_sizes[5] / B;
    int L = in_sizes[6] / (B * N * 4);
    float* out = (float*)d_out;

    size_t smem = (size_t)CAP_M * CAP_N * sizeof(float);  // 72000 B
    static int attr_set = 0;
    if (!attr_set) {
        cudaFuncSetAttribute(hungarian_kernel,
                             cudaFuncAttributeMaxDynamicSharedMemorySize, (int)smem);
        attr_set = 1;
    }

    hungarian_kernel<<<B, 128, smem>>>(mask, (const float4*)pred, (const float4*)tgt,
                                       (const float4*)aux_pred, B, N, M, L);
    int nbce = (B * N * (1 + L) + 255) / 256;
    int nblocks = nbce + B;
    bce_final_kernel<<<nblocks, 256>>>(obj, aux_obj, cls, label, out,
                                       B, N, L, C, nbce, nblocks);
}

// round 5
// speedup vs baseline: 5.6330x; 1.6098x over previous
#include <cuda_runtime.h>
#include <math.h>
#include <float.h>

// Problem capacities (B=32, N=300, M=60, L=5, C=1000)
#define CAP_B 32
#define CAP_N 300
#define CAP_M 60
#define HT 320             // hungarian block threads (>= CAP_N)
#define NWARP (HT / 32)
#define BCE_CAP_BLOCKS 512

// ---------------- device scratch (no allocations allowed) ----------------
__device__ int      g_k[CAP_B];
__device__ float    g_obj_t[CAP_B * CAP_N];
__device__ double   g_cls[CAP_B];
__device__ double   g_pair[CAP_B * 4];              // {bbox, giou, aux_bbox, aux_giou}
__device__ double   g_bce[BCE_CAP_BLOCKS * 2];
__device__ unsigned g_sem;                          // zero-init; reset at end of each run

// ---------------- helpers ----------------
__device__ __forceinline__ float giou_f(
    float ax0, float ay0, float ax1, float ay1,
    float bx0, float by0, float bx1, float by1)
{
    const float EPS = 1e-7f;
    float area_a = (ax1 - ax0) * (ay1 - ay0);
    float area_b = (bx1 - bx0) * (by1 - by0);
    float ltx = fmaxf(ax0, bx0), lty = fmaxf(ay0, by0);
    float rbx = fminf(ax1, bx1), rby = fminf(ay1, by1);
    float wx = fmaxf(rbx - ltx, 0.0f), wy = fmaxf(rby - lty, 0.0f);
    float inter = wx * wy;
    float uni = area_a + area_b - inter;
    float iou = inter / (uni + EPS);
    float ex = fmaxf(fmaxf(ax1, bx1) - fminf(ax0, bx0), 0.0f);
    float ey = fmaxf(fmaxf(ay1, by1) - fminf(ay0, by0), 0.0f);
    float enc = ex * ey;
    return iou - (enc - uni) / (enc + EPS);
}

__device__ __forceinline__ float giou_cxcywh(float4 p, float4 q)
{
    return giou_f(p.x - p.z * 0.5f, p.y - p.w * 0.5f, p.x + p.z * 0.5f, p.y + p.w * 0.5f,
                  q.x - q.z * 0.5f, q.y - q.w * 0.5f, q.x + q.z * 0.5f, q.y + q.w * 0.5f);
}

__device__ __forceinline__ float l1_cxcywh(float4 p, float4 q)
{
    return fabsf(p.x - q.x) + fabsf(p.y - q.y) + fabsf(p.z - q.z) + fabsf(p.w - q.w);
}

__device__ __forceinline__ float bce_f(float x, float t)
{
    return fmaxf(x, 0.0f) - x * t + log1pf(expf(-fabsf(x)));
}

// ordered mapping (ascending) for f32
__device__ __forceinline__ unsigned order_f32(float f)
{
    unsigned u = __float_as_uint(f);
    return (u & 0x80000000u) ? ~u : (u | 0x80000000u);
}
__device__ __forceinline__ float unorder_f32(unsigned k)
{
    unsigned u = (k & 0x80000000u) ? (k & 0x7fffffffu) : ~k;
    return __uint_as_float(u);
}
__device__ __forceinline__ unsigned long long pack_vc(float v, unsigned col)
{
    return ((unsigned long long)order_f32(v) << 32) | (unsigned long long)col;
}

// ---------------- K1: LAPJV-style block-wide LAP + pair losses --------
// One block of 320 threads per batch (1 column per thread). Cost in smem.
__global__ void __launch_bounds__(HT, 1)
hungarian_kernel(const float* __restrict__ mask,
                 const float4* __restrict__ pred,
                 const float4* __restrict__ tgt,
                 const float4* __restrict__ aux_pred,
                 int B, int N, int M, int L)
{
    extern __shared__ float cost_sh[];               // [k][N] row-major
    const unsigned FULL = 0xffffffffu;
    int b = blockIdx.x;
    int tid = threadIdx.x;
    int lane = tid & 31, wid = tid >> 5;
    int col = tid;
    bool active = (col < N);

    __shared__ float4 pred_sh[CAP_N];
    __shared__ float4 tgt_sh[CAP_M];
    __shared__ float  u_sh[CAP_M];
    __shared__ float  margin_sh[CAP_M];
    __shared__ int    gcol_sh[CAP_M];
    __shared__ int    vid_sh[CAP_M];
    __shared__ int    row4col_sh[CAP_N];   // col -> row (0-based), -1 free
    __shared__ int    col4row_sh[CAP_M];   // row -> col, -1 free
    __shared__ int    way_sh[CAP_N];       // predecessor row along shortest path
    __shared__ int    queue_sh[CAP_M + 4];
    __shared__ unsigned wval_sh[NWARP];
    __shared__ int    wcol_sh[NWARP];
    __shared__ int    s_k, s_nf, s_i, s_j0;
    __shared__ float  s_base, s_minval;
    __shared__ double s_red[4 * NWARP];

    if (active) row4col_sh[col] = -1;
    if (tid < M) col4row_sh[tid] = -1;
    for (int j = tid; j < N; j += HT) pred_sh[j] = pred[b * N + j];
    for (int t = tid; t < M; t += HT) tgt_sh[t] = tgt[b * M + t];

    const float* mrow = mask + (size_t)b * M;
    if (wid == 0) {
        bool v0 = (lane < M) && (mrow[lane] > 0.5f);
        bool v1 = (32 + lane < M) && (mrow[32 + lane] > 0.5f);
        unsigned b0 = __ballot_sync(FULL, v0);
        unsigned b1 = __ballot_sync(FULL, v1);
        unsigned lm = (1u << lane) - 1u;
        if (v0) vid_sh[__popc(b0 & lm)] = lane;
        if (v1) vid_sh[__popc(b0) + __popc(b1 & lm)] = 32 + lane;
        if (lane == 0) {
            s_k = __popc(b0) + __popc(b1);
            g_k[b] = s_k;
        }
    }
    __syncthreads();
    int k = s_k;

    // --- build cost matrix in smem: cost[i][j] = 5*L1 - 2*GIoU ---
    for (int idx = tid; idx < k * N; idx += HT) {
        int i = idx / N;
        int j = idx - i * N;
        float4 p = pred_sh[j];
        float4 q = tgt_sh[vid_sh[i]];
        cost_sh[idx] = 5.0f * l1_cxcywh(p, q) - 2.0f * giou_cxcywh(p, q);
    }
    __syncthreads();

    // --- greedy: per-row (min1, argmin, min2) — rows striped over 10 warps ---
    for (int i = wid; i < k; i += NWARP) {
        const float* crow = cost_sh + i * N;
        unsigned long long b1 = 0xFFFFFFFFFFFFFFFFull;
        unsigned long long b2 = 0xFFFFFFFFFFFFFFFFull;
        #pragma unroll
        for (int q = 0; q < 10; q++) {
            int c = lane + 32 * q;
            if (c < N) {
                unsigned long long pk = pack_vc(crow[c], (unsigned)c);
                if (pk < b1) { b2 = b1; b1 = pk; }
                else if (pk < b2) b2 = pk;
            }
        }
        #pragma unroll
        for (int off = 16; off; off >>= 1) {
            unsigned long long o1 = __shfl_xor_sync(FULL, b1, off);
            unsigned long long o2 = __shfl_xor_sync(FULL, b2, off);
            unsigned long long hi = (b1 < o1) ? o1 : b1;
            b1 = (b1 < o1) ? b1 : o1;
            unsigned long long lo2 = (b2 < o2) ? b2 : o2;
            b2 = (hi < lo2) ? hi : lo2;
        }
        if (lane == 0) {
            float m1 = unorder_f32((unsigned)(b1 >> 32));
            float m2 = unorder_f32((unsigned)(b2 >> 32));
            u_sh[i] = m1;
            gcol_sh[i] = (int)(b1 & 0xFFFFFFFFull);
            margin_sh[i] = m2 - m1;
        }
    }
    __syncthreads();

    // --- conflict resolution: contested column goes to max-margin row ---
    if (tid == 0) {
        int nf = 0;
        for (int i = 0; i < k; i++) {
            int c = gcol_sh[i];
            int own = row4col_sh[c];
            if (own < 0) {
                row4col_sh[c] = i; col4row_sh[i] = c;
            } else if (margin_sh[i] > margin_sh[own]) {
                row4col_sh[c] = i; col4row_sh[i] = c;
                col4row_sh[own] = -1;
                queue_sh[nf++] = own;
            } else {
                queue_sh[nf++] = i;
            }
        }
        s_nf = nf;
    }
    __syncthreads();
    int nf = s_nf;

    // --- block-wide SSP augmentation (scipy formulation, duals updated per path) ---
    float v = 0.0f;  // column dual, register (one col per thread)
    for (int qi = 0; qi < nf; qi++) {
        int cur = queue_sh[qi];
        float minv = INFINITY;
        int way = 0;
        bool inSC = false;
        if (tid == 0) {
            s_i = cur;
            s_base = -u_sh[cur];   // minVal(=0) - u[cur]
            s_minval = 0.0f;
        }
        __syncthreads();
        while (true) {
            unsigned key = 0xFFFFFFFFu;
            if (active && !inSC) {
                float r = s_base + cost_sh[s_i * N + col] - v;
                if (r < minv) { minv = r; way = s_i; }
                key = order_f32(minv);
            }
            unsigned kmin = __reduce_min_sync(FULL, key);
            unsigned cnd = (key == kmin) ? (unsigned)col : 0x7FFFFFFFu;
            unsigned cmin = __reduce_min_sync(FULL, cnd);
            if (lane == 0) { wval_sh[wid] = kmin; wcol_sh[wid] = (int)cmin; }
            __syncthreads();
            if (tid == 0) {
                unsigned bk = 0xFFFFFFFFu;
                int bc = 0x7FFFFFFF;
                #pragma unroll
                for (int w = 0; w < NWARP; w++) {
                    unsigned kv = wval_sh[w];
                    int cv = wcol_sh[w];
                    if (kv < bk || (kv == bk && cv < bc)) { bk = kv; bc = cv; }
                }
                float d = unorder_f32(bk);
                s_minval = d;
                s_j0 = bc;
                int r0 = row4col_sh[bc];
                s_i = r0;
                if (r0 >= 0) s_base = d - u_sh[r0];
            }
            __syncthreads();
            if (col == s_j0) { inSC = true; way_sh[col] = way; }
            if (s_i < 0) break;
        }
        __syncthreads();   // way_sh[sink] visible to tid 0
        // dual updates (once per augmentation)
        float mv = s_minval;
        if (active && inSC) {
            float diff = mv - minv;
            v -= diff;
            int r = row4col_sh[col];
            if (r >= 0) u_sh[r] += diff;   // distinct r per col
        }
        if (tid == 0) u_sh[cur] += mv;
        __syncthreads();   // duals done before row4col changes
        if (tid == 0) {
            int j = s_j0;
            while (true) {
                int i = way_sh[j];
                row4col_sh[j] = i;
                int jn = col4row_sh[i];
                col4row_sh[i] = j;
                if (i == cur) break;
                j = jn;
            }
        }
        __syncthreads();
    }

    // --- pair losses + obj_t (one column per thread) ---
    double bb = 0.0, gg = 0.0, ab = 0.0, ag = 0.0;
    if (active) {
        int r = row4col_sh[col];
        g_obj_t[b * N + col] = (r >= 0) ? 1.0f : 0.0f;
        if (r >= 0) {
            float4 p = pred_sh[col];
            float4 t = tgt_sh[vid_sh[r]];
            bb = (double)l1_cxcywh(p, t);
            gg = (double)(1.0f - giou_cxcywh(p, t));
            for (int l = 0; l < L; l++) {
                float4 a = aux_pred[((size_t)l * B + b) * N + col];
                ab += (double)l1_cxcywh(a, t);
                ag += (double)(1.0f - giou_cxcywh(a, t));
            }
        }
    }
    #pragma unroll
    for (int off = 16; off; off >>= 1) {
        bb += __shfl_xor_sync(FULL, bb, off);
        gg += __shfl_xor_sync(FULL, gg, off);
        ab += __shfl_xor_sync(FULL, ab, off);
        ag += __shfl_xor_sync(FULL, ag, off);
    }
    if (lane == 0) {
        s_red[wid] = bb;
        s_red[NWARP + wid] = gg;
        s_red[2 * NWARP + wid] = ab;
        s_red[3 * NWARP + wid] = ag;
    }
    __syncthreads();
    if (tid == 0) {
        double t0 = 0.0, t1 = 0.0, t2 = 0.0, t3 = 0.0;
        #pragma unroll
        for (int w = 0; w < NWARP; w++) {
            t0 += s_red[w];
            t1 += s_red[NWARP + w];
            t2 += s_red[2 * NWARP + w];
            t3 += s_red[3 * NWARP + w];
        }
        g_pair[b * 4 + 0] = t0;
        g_pair[b * 4 + 1] = t1;
        g_pair[b * 4 + 2] = t2;
        g_pair[b * 4 + 3] = t3;
    }
}

// ---------------- K2: BCE + cls log-softmax + last-block final reduction ----------
__global__ void bce_final_kernel(const float* __restrict__ obj,
                                 const float* __restrict__ aux_obj,
                                 const float* __restrict__ cls,
                                 const int* __restrict__ label,
                                 float* __restrict__ out,
                                 int B, int N, int L, int C,
                                 int nbce, int nblocks)
{
    int tid = threadIdx.x;
    int bid = blockIdx.x;
    __shared__ double rm[256];
    __shared__ double ra[256];
    __shared__ int s_last;

    if (bid >= nbce) {
        int b = bid - nbce;
        __shared__ float sred[256];
        const float* x = cls + (size_t)b * C;
        float m = -FLT_MAX;
        for (int c = tid; c < C; c += 256) m = fmaxf(m, x[c]);
        sred[tid] = m;
        __syncthreads();
        for (int off = 128; off; off >>= 1) {
            if (tid < off) sred[tid] = fmaxf(sred[tid], sred[tid + off]);
            __syncthreads();
        }
        m = sred[0];
        __syncthreads();
        float s = 0.0f;
        for (int c = tid; c < C; c += 256) s += expf(x[c] - m);
        sred[tid] = s;
        __syncthreads();
        for (int off = 128; off; off >>= 1) {
            if (tid < off) sred[tid] += sred[tid + off];
            __syncthreads();
        }
        if (tid == 0) {
            g_cls[b] = (double)(m + logf(sred[0]) - x[label[b]]);
            __threadfence();
            atomicAdd(&g_sem, 1u);
        }
        return;
    }

    int idx = bid * 256 + tid;
    int mt = B * N;
    int total = mt * (1 + L);
    double vm = 0.0, va = 0.0;
    if (idx < total) {
        if (idx < mt) {
            vm = (double)bce_f(obj[idx], g_obj_t[idx]);
        } else {
            int a = idx - mt;
            va = (double)bce_f(aux_obj[a], g_obj_t[a % mt]);
        }
    }
    rm[tid] = vm;
    ra[tid] = va;
    __syncthreads();
    for (int off = 128; off; off >>= 1) {
        if (tid < off) { rm[tid] += rm[tid + off]; ra[tid] += ra[tid + off]; }
        __syncthreads();
    }
    if (tid == 0) {
        g_bce[2 * bid + 0] = rm[0];
        g_bce[2 * bid + 1] = ra[0];
        __threadfence();
        unsigned t = atomicAdd(&g_sem, 1u);
        s_last = (t == (unsigned)(nblocks - 1)) ? 1 : 0;
    }
    __syncthreads();
    if (!s_last) return;
    __threadfence();

    double om = 0.0, oa = 0.0;
    for (int i = tid; i < nbce; i += 256) {
        om += g_bce[2 * i + 0];
        oa += g_bce[2 * i + 1];
    }
    rm[tid] = om;
    ra[tid] = oa;
    __syncthreads();
    for (int off = 128; off; off >>= 1) {
        if (tid < off) { rm[tid] += rm[tid + off]; ra[tid] += ra[tid + off]; }
        __syncthreads();
    }
    if (tid == 0) {
        double objs = rm[0], aobj = ra[0];
        double nb = 0.0, clsl = 0.0, bbox = 0.0, gi = 0.0, abx = 0.0, agx = 0.0;
        for (int bi = 0; bi < B; bi++) {
            nb   += (double)g_k[bi];
            clsl += g_cls[bi];
            bbox += g_pair[bi * 4 + 0];
            gi   += g_pair[bi * 4 + 1];
            abx  += g_pair[bi * 4 + 2];
            agx  += g_pair[bi * 4 + 3];
        }
        if (nb < 1.0) nb = 1.0;
        double BN = (double)B * (double)N;
        double tot = clsl / (double)B
                   + 5.0 * bbox / nb
                   + 2.0 * gi / nb
                   + objs / BN
                   + (5.0 * abx / nb + 2.0 * agx / nb + aobj / BN) * 0.5 / (double)L;
        out[0] = (float)tot;
        g_sem = 0u;  // reset for next replay
    }
}

// ---------------- launch ----------------
extern "C" void kernel_launch(void* const* d_in, const int* in_sizes, int n_in,
                              void* d_out, int out_size)
{
    const float* cls      = (const float*)d_in[0];
    const int*   label    = (const int*)d_in[1];
    const float* pred     = (const float*)d_in[2];
    const float* obj      = (const float*)d_in[3];
    const float* tgt      = (const float*)d_in[4];
    const float* mask     = (const float*)d_in[5];
    const float* aux_pred = (const float*)d_in[6];
    const float* aux_obj  = (const float*)d_in[7];

    int B = in_sizes[1];
    int C = in_sizes[0] / B;
    int N = in_sizes[3] / B;
    int M = in_sizes[5] / B;
    int L = in_sizes[6] / (B * N * 4);
    float* out = (float*)d_out;

    size_t smem = (size_t)CAP_M * CAP_N * sizeof(float);  // 72000 B
    static int attr_set = 0;
    if (!attr_set) {
        cudaFuncSetAttribute(hungarian_kernel,
                             cudaFuncAttributeMaxDynamicSharedMemorySize, (int)smem);
        attr_set = 1;
    }

    hungarian_kernel<<<B, HT, smem>>>(mask, (const float4*)pred, (const float4*)tgt,
                                      (const float4*)aux_pred, B, N, M, L);
    int nbce = (B * N * (1 + L) + 255) / 256;
    int nblocks = nbce + B;
    bce_final_kernel<<<nblocks, 256>>>(obj, aux_obj, cls, label, out,
                                       B, N, L, C, nbce, nblocks);
}

// round 6
// speedup vs baseline: 6.6047x; 1.1725x over previous
#include <cuda_runtime.h>
#include <math.h>
#include <float.h>

// Problem capacities (B=32, N=300, M=60, L=5, C=1000)
#define CAP_B 32
#define CAP_N 300
#define CAP_M 60
#define HT 320             // hungarian block threads (>= CAP_N)
#define NWARP (HT / 32)

// ---------------- device scratch (no allocations allowed) ----------------
__device__ int      g_k[CAP_B];
__device__ double   g_cls[CAP_B];
__device__ double   g_pair[CAP_B * 6];   // {bbox, giou, aux_bbox, aux_giou, bce, aux_bce}
__device__ unsigned g_sem;               // zero-init; reset at end of each run

// ---------------- helpers ----------------
__device__ __forceinline__ float giou_f(
    float ax0, float ay0, float ax1, float ay1,
    float bx0, float by0, float bx1, float by1)
{
    const float EPS = 1e-7f;
    float area_a = (ax1 - ax0) * (ay1 - ay0);
    float area_b = (bx1 - bx0) * (by1 - by0);
    float ltx = fmaxf(ax0, bx0), lty = fmaxf(ay0, by0);
    float rbx = fminf(ax1, bx1), rby = fminf(ay1, by1);
    float wx = fmaxf(rbx - ltx, 0.0f), wy = fmaxf(rby - lty, 0.0f);
    float inter = wx * wy;
    float uni = area_a + area_b - inter;
    float iou = inter / (uni + EPS);
    float ex = fmaxf(fmaxf(ax1, bx1) - fminf(ax0, bx0), 0.0f);
    float ey = fmaxf(fmaxf(ay1, by1) - fminf(ay0, by0), 0.0f);
    float enc = ex * ey;
    return iou - (enc - uni) / (enc + EPS);
}

__device__ __forceinline__ float giou_cxcywh(float4 p, float4 q)
{
    return giou_f(p.x - p.z * 0.5f, p.y - p.w * 0.5f, p.x + p.z * 0.5f, p.y + p.w * 0.5f,
                  q.x - q.z * 0.5f, q.y - q.w * 0.5f, q.x + q.z * 0.5f, q.y + q.w * 0.5f);
}

__device__ __forceinline__ float l1_cxcywh(float4 p, float4 q)
{
    return fabsf(p.x - q.x) + fabsf(p.y - q.y) + fabsf(p.z - q.z) + fabsf(p.w - q.w);
}

__device__ __forceinline__ float bce_f(float x, float t)
{
    return fmaxf(x, 0.0f) - x * t + log1pf(expf(-fabsf(x)));
}

__device__ __forceinline__ unsigned order_f32(float f)
{
    unsigned u = __float_as_uint(f);
    return (u & 0x80000000u) ? ~u : (u | 0x80000000u);
}
__device__ __forceinline__ float unorder_f32(unsigned k)
{
    unsigned u = (k & 0x80000000u) ? (k & 0x7fffffffu) : ~k;
    return __uint_as_float(u);
}
__device__ __forceinline__ unsigned long long pack_vc(float v, unsigned col)
{
    return ((unsigned long long)order_f32(v) << 32) | (unsigned long long)col;
}

// ---------------- K1: block-wide LAP (greedy + SSP) + pair/BCE losses --------
// One block of 320 threads per batch (1 column per thread). Cost in smem.
__global__ void __launch_bounds__(HT, 1)
hungarian_kernel(const float* __restrict__ mask,
                 const float4* __restrict__ pred,
                 const float4* __restrict__ tgt,
                 const float4* __restrict__ aux_pred,
                 const float* __restrict__ obj,
                 const float* __restrict__ aux_obj,
                 int B, int N, int M, int L)
{
    extern __shared__ float cost_sh[];               // [k][N] row-major
    const unsigned FULL = 0xffffffffu;
    int b = blockIdx.x;
    int tid = threadIdx.x;
    int lane = tid & 31, wid = tid >> 5;
    int col = tid;
    bool active = (col < N);

    __shared__ float4 pred_sh[CAP_N];
    __shared__ float4 tgt_sh[CAP_M];
    __shared__ float  u_sh[CAP_M];
    __shared__ float  margin_sh[CAP_M];
    __shared__ int    gcol_sh[CAP_M];
    __shared__ int    vid_sh[CAP_M];
    __shared__ int    row4col_sh[CAP_N];   // col -> row (0-based), -1 free
    __shared__ int    col4row_sh[CAP_M];   // row -> col, -1 free
    __shared__ int    way_sh[CAP_N];       // predecessor row along shortest path
    __shared__ int    queue_sh[CAP_M + 4];
    __shared__ unsigned long long wpack_sh[2][NWARP];
    __shared__ int    s_k, s_nf;
    __shared__ double s_red[6 * NWARP];

    if (active) row4col_sh[col] = -1;
    if (tid < M) col4row_sh[tid] = -1;
    for (int j = tid; j < N; j += HT) pred_sh[j] = pred[b * N + j];
    for (int t = tid; t < M; t += HT) tgt_sh[t] = tgt[b * M + t];

    const float* mrow = mask + (size_t)b * M;
    if (wid == 0) {
        bool v0 = (lane < M) && (mrow[lane] > 0.5f);
        bool v1 = (32 + lane < M) && (mrow[32 + lane] > 0.5f);
        unsigned b0 = __ballot_sync(FULL, v0);
        unsigned b1 = __ballot_sync(FULL, v1);
        unsigned lm = (1u << lane) - 1u;
        if (v0) vid_sh[__popc(b0 & lm)] = lane;
        if (v1) vid_sh[__popc(b0) + __popc(b1 & lm)] = 32 + lane;
        if (lane == 0) {
            s_k = __popc(b0) + __popc(b1);
            g_k[b] = s_k;
        }
    }
    __syncthreads();
    int k = s_k;

    // --- build cost matrix in smem: cost[i][j] = 5*L1 - 2*GIoU ---
    for (int idx = tid; idx < k * N; idx += HT) {
        int i = idx / N;
        int j = idx - i * N;
        float4 p = pred_sh[j];
        float4 q = tgt_sh[vid_sh[i]];
        cost_sh[idx] = 5.0f * l1_cxcywh(p, q) - 2.0f * giou_cxcywh(p, q);
    }
    __syncthreads();

    // --- greedy: per-row (min1, argmin, min2) — rows striped over 10 warps ---
    for (int i = wid; i < k; i += NWARP) {
        const float* crow = cost_sh + i * N;
        unsigned long long b1 = 0xFFFFFFFFFFFFFFFFull;
        unsigned long long b2 = 0xFFFFFFFFFFFFFFFFull;
        #pragma unroll
        for (int q = 0; q < 10; q++) {
            int c = lane + 32 * q;
            if (c < N) {
                unsigned long long pk = pack_vc(crow[c], (unsigned)c);
                if (pk < b1) { b2 = b1; b1 = pk; }
                else if (pk < b2) b2 = pk;
            }
        }
        #pragma unroll
        for (int off = 16; off; off >>= 1) {
            unsigned long long o1 = __shfl_xor_sync(FULL, b1, off);
            unsigned long long o2 = __shfl_xor_sync(FULL, b2, off);
            unsigned long long hi = (b1 < o1) ? o1 : b1;
            b1 = (b1 < o1) ? b1 : o1;
            unsigned long long lo2 = (b2 < o2) ? b2 : o2;
            b2 = (hi < lo2) ? hi : lo2;
        }
        if (lane == 0) {
            float m1 = unorder_f32((unsigned)(b1 >> 32));
            float m2 = unorder_f32((unsigned)(b2 >> 32));
            u_sh[i] = m1;
            gcol_sh[i] = (int)(b1 & 0xFFFFFFFFull);
            margin_sh[i] = m2 - m1;
        }
    }
    __syncthreads();

    // --- conflict resolution: contested column goes to max-margin row ---
    if (tid == 0) {
        int nf = 0;
        for (int i = 0; i < k; i++) {
            int c = gcol_sh[i];
            int own = row4col_sh[c];
            if (own < 0) {
                row4col_sh[c] = i; col4row_sh[i] = c;
            } else if (margin_sh[i] > margin_sh[own]) {
                row4col_sh[c] = i; col4row_sh[i] = c;
                col4row_sh[own] = -1;
                queue_sh[nf++] = own;
            } else {
                queue_sh[nf++] = i;
            }
        }
        s_nf = nf;
    }
    __syncthreads();
    int nf = s_nf;

    // --- block-wide SSP augmentation: ONE barrier per Dijkstra step ---
    float v = 0.0f;  // column dual (register; one col per thread)
    for (int qi = 0; qi < nf; qi++) {
        int cur = queue_sh[qi];
        float minv = INFINITY;
        int way = 0;
        bool inSC = false;
        int i_cur = cur;
        float base = -u_sh[cur];
        float mv;
        int sink;
        int par = 0;
        while (true) {
            unsigned key = 0xFFFFFFFFu;
            if (active && !inSC) {
                float r = base + cost_sh[i_cur * N + col] - v;
                if (r < minv) { minv = r; way = i_cur; }
                key = order_f32(minv);
            }
            unsigned kmin = __reduce_min_sync(FULL, key);
            unsigned cnd = (key == kmin) ? (unsigned)col : 0x7FFFFFFFu;
            unsigned cmin = __reduce_min_sync(FULL, cnd);
            if (lane == 0)
                wpack_sh[par][wid] = ((unsigned long long)kmin << 32) | cmin;
            __syncthreads();
            unsigned long long best = wpack_sh[par][0];
            #pragma unroll
            for (int w = 1; w < NWARP; w++) {
                unsigned long long o = wpack_sh[par][w];
                if (o < best) best = o;
            }
            par ^= 1;
            float d = unorder_f32((unsigned)(best >> 32));
            int j0 = (int)(best & 0xFFFFFFFFull);
            if (col == j0) { inSC = true; way_sh[col] = way; }
            int r0 = row4col_sh[j0];       // uniform broadcast read
            if (r0 < 0) { mv = d; sink = j0; break; }
            base = d - u_sh[r0];
            i_cur = r0;
        }
        __syncthreads();   // way_sh[sink] + loop reads done before dual/assign updates
        // dual updates (once per augmentation)
        if (active && inSC) {
            float diff = mv - minv;
            v -= diff;
            int r = row4col_sh[col];
            if (r >= 0) u_sh[r] += diff;   // distinct r per col
        }
        if (tid == 0) u_sh[cur] += mv;
        __syncthreads();   // duals settled before assignment rewiring
        if (tid == 0) {
            int j = sink;
            while (true) {
                int i = way_sh[j];
                row4col_sh[j] = i;
                int jn = col4row_sh[i];
                col4row_sh[i] = j;
                if (i == cur) break;
                j = jn;
            }
        }
        __syncthreads();
    }

    // --- pair losses + BCE (one column per thread) ---
    double bb = 0.0, gg = 0.0, ab = 0.0, ag = 0.0, bm = 0.0, ba = 0.0;
    if (active) {
        int r = row4col_sh[col];
        float ot = (r >= 0) ? 1.0f : 0.0f;
        bm = (double)bce_f(obj[b * N + col], ot);
        for (int l = 0; l < L; l++)
            ba += (double)bce_f(aux_obj[((size_t)l * B + b) * N + col], ot);
        if (r >= 0) {
            float4 p = pred_sh[col];
            float4 t = tgt_sh[vid_sh[r]];
            bb = (double)l1_cxcywh(p, t);
            gg = (double)(1.0f - giou_cxcywh(p, t));
            for (int l = 0; l < L; l++) {
                float4 a = aux_pred[((size_t)l * B + b) * N + col];
                ab += (double)l1_cxcywh(a, t);
                ag += (double)(1.0f - giou_cxcywh(a, t));
            }
        }
    }
    #pragma unroll
    for (int off = 16; off; off >>= 1) {
        bb += __shfl_xor_sync(FULL, bb, off);
        gg += __shfl_xor_sync(FULL, gg, off);
        ab += __shfl_xor_sync(FULL, ab, off);
        ag += __shfl_xor_sync(FULL, ag, off);
        bm += __shfl_xor_sync(FULL, bm, off);
        ba += __shfl_xor_sync(FULL, ba, off);
    }
    if (lane == 0) {
        s_red[wid] = bb;
        s_red[NWARP + wid] = gg;
        s_red[2 * NWARP + wid] = ab;
        s_red[3 * NWARP + wid] = ag;
        s_red[4 * NWARP + wid] = bm;
        s_red[5 * NWARP + wid] = ba;
    }
    __syncthreads();
    if (tid < 6) {
        double t0 = 0.0;
        #pragma unroll
        for (int w = 0; w < NWARP; w++) t0 += s_red[tid * NWARP + w];
        g_pair[b * 6 + tid] = t0;
    }
}

// ---------------- K2: cls log-softmax (1 block per batch) + last-block final ------
__global__ void cls_final_kernel(const float* __restrict__ cls,
                                 const int* __restrict__ label,
                                 float* __restrict__ out,
                                 int B, int N, int L, int C)
{
    int tid = threadIdx.x;
    int b = blockIdx.x;
    __shared__ float sred[256];
    __shared__ int s_last;

    const float* x = cls + (size_t)b * C;
    float m = -FLT_MAX;
    for (int c = tid; c < C; c += 256) m = fmaxf(m, x[c]);
    sred[tid] = m;
    __syncthreads();
    for (int off = 128; off; off >>= 1) {
        if (tid < off) sred[tid] = fmaxf(sred[tid], sred[tid + off]);
        __syncthreads();
    }
    m = sred[0];
    __syncthreads();
    float s = 0.0f;
    for (int c = tid; c < C; c += 256) s += expf(x[c] - m);
    sred[tid] = s;
    __syncthreads();
    for (int off = 128; off; off >>= 1) {
        if (tid < off) sred[tid] += sred[tid + off];
        __syncthreads();
    }
    if (tid == 0) {
        g_cls[b] = (double)(m + logf(sred[0]) - x[label[b]]);
        __threadfence();
        unsigned t = atomicAdd(&g_sem, 1u);
        s_last = (t == (unsigned)(B - 1)) ? 1 : 0;
    }
    __syncthreads();
    if (!s_last) return;
    __threadfence();

    if (tid == 0) {
        double nb = 0.0, clsl = 0.0, bbox = 0.0, gi = 0.0;
        double abx = 0.0, agx = 0.0, objs = 0.0, aobj = 0.0;
        for (int bi = 0; bi < B; bi++) {
            nb   += (double)g_k[bi];
            clsl += g_cls[bi];
            bbox += g_pair[bi * 6 + 0];
            gi   += g_pair[bi * 6 + 1];
            abx  += g_pair[bi * 6 + 2];
            agx  += g_pair[bi * 6 + 3];
            objs += g_pair[bi * 6 + 4];
            aobj += g_pair[bi * 6 + 5];
        }
        if (nb < 1.0) nb = 1.0;
        double BN = (double)B * (double)N;
        double tot = clsl / (double)B
                   + 5.0 * bbox / nb
                   + 2.0 * gi / nb
                   + objs / BN
                   + (5.0 * abx / nb + 2.0 * agx / nb + aobj / BN) * 0.5 / (double)L;
        out[0] = (float)tot;
        g_sem = 0u;  // reset for next replay
    }
}

// ---------------- launch ----------------
extern "C" void kernel_launch(void* const* d_in, const int* in_sizes, int n_in,
                              void* d_out, int out_size)
{
    const float* cls      = (const float*)d_in[0];
    const int*   label    = (const int*)d_in[1];
    const float* pred     = (const float*)d_in[2];
    const float* obj      = (const float*)d_in[3];
    const float* tgt      = (const float*)d_in[4];
    const float* mask     = (const float*)d_in[5];
    const float* aux_pred = (const float*)d_in[6];
    const float* aux_obj  = (const float*)d_in[7];

    int B = in_sizes[1];
    int C = in_sizes[0] / B;
    int N = in_sizes[3] / B;
    int M = in_sizes[5] / B;
    int L = in_sizes[6] / (B * N * 4);
    float* out = (float*)d_out;

    size_t smem = (size_t)CAP_M * CAP_N * sizeof(float);  // 72000 B
    static int attr_set = 0;
    if (!attr_set) {
        cudaFuncSetAttribute(hungarian_kernel,
                             cudaFuncAttributeMaxDynamicSharedMemorySize, (int)smem);
        attr_set = 1;
    }

    hungarian_kernel<<<B, HT, smem>>>(mask, (const float4*)pred, (const float4*)tgt,
                                      (const float4*)aux_pred, obj, aux_obj,
                                      B, N, M, L);
    cls_final_kernel<<<B, 256>>>(cls, label, out, B, N, L, C);
}

// round 7
// speedup vs baseline: 6.7119x; 1.0162x over previous
#include <cuda_runtime.h>
#include <math.h>
#include <float.h>

// Problem capacities (B=32, N=300, M=60, L=5, C=1000)
#define CAP_B 32
#define CAP_N 300
#define CAP_M 60
#define HT 320             // block threads (>= CAP_N)
#define NWARP (HT / 32)

// ---------------- device scratch (no allocations allowed) ----------------
__device__ int      g_k[CAP_B];
__device__ double   g_cls[CAP_B];
__device__ double   g_pair[CAP_B * 6];   // {bbox, giou, aux_bbox, aux_giou, bce, aux_bce}
__device__ unsigned g_sem;               // zero-init; reset by last block each run

// ---------------- helpers ----------------
__device__ __forceinline__ float giou_f(
    float ax0, float ay0, float ax1, float ay1,
    float bx0, float by0, float bx1, float by1)
{
    const float EPS = 1e-7f;
    float area_a = (ax1 - ax0) * (ay1 - ay0);
    float area_b = (bx1 - bx0) * (by1 - by0);
    float ltx = fmaxf(ax0, bx0), lty = fmaxf(ay0, by0);
    float rbx = fminf(ax1, bx1), rby = fminf(ay1, by1);
    float wx = fmaxf(rbx - ltx, 0.0f), wy = fmaxf(rby - lty, 0.0f);
    float inter = wx * wy;
    float uni = area_a + area_b - inter;
    float iou = inter / (uni + EPS);
    float ex = fmaxf(fmaxf(ax1, bx1) - fminf(ax0, bx0), 0.0f);
    float ey = fmaxf(fmaxf(ay1, by1) - fminf(ay0, by0), 0.0f);
    float enc = ex * ey;
    return iou - (enc - uni) / (enc + EPS);
}

__device__ __forceinline__ float giou_cxcywh(float4 p, float4 q)
{
    return giou_f(p.x - p.z * 0.5f, p.y - p.w * 0.5f, p.x + p.z * 0.5f, p.y + p.w * 0.5f,
                  q.x - q.z * 0.5f, q.y - q.w * 0.5f, q.x + q.z * 0.5f, q.y + q.w * 0.5f);
}

__device__ __forceinline__ float l1_cxcywh(float4 p, float4 q)
{
    return fabsf(p.x - q.x) + fabsf(p.y - q.y) + fabsf(p.z - q.z) + fabsf(p.w - q.w);
}

__device__ __forceinline__ float bce_f(float x, float t)
{
    return fmaxf(x, 0.0f) - x * t + log1pf(expf(-fabsf(x)));
}

__device__ __forceinline__ unsigned order_f32(float f)
{
    unsigned u = __float_as_uint(f);
    return (u & 0x80000000u) ? ~u : (u | 0x80000000u);
}
__device__ __forceinline__ float unorder_f32(unsigned k)
{
    unsigned u = (k & 0x80000000u) ? (k & 0x7fffffffu) : ~k;
    return __uint_as_float(u);
}
__device__ __forceinline__ unsigned long long pack_vc(float v, unsigned col)
{
    return ((unsigned long long)order_f32(v) << 32) | (unsigned long long)col;
}

// ---------------- single fused kernel: LAP + all losses + final fold --------------
__global__ void __launch_bounds__(HT, 1)
detr_kernel(const float* __restrict__ mask,
            const float4* __restrict__ pred,
            const float4* __restrict__ tgt,
            const float4* __restrict__ aux_pred,
            const float* __restrict__ obj,
            const float* __restrict__ aux_obj,
            const float* __restrict__ cls,
            const int* __restrict__ label,
            float* __restrict__ out,
            int B, int N, int M, int L, int C)
{
    extern __shared__ float cost_sh[];               // [k][N] row-major
    const unsigned FULL = 0xffffffffu;
    int b = blockIdx.x;
    int tid = threadIdx.x;
    int lane = tid & 31, wid = tid >> 5;
    int col = tid;
    bool active = (col < N);

    __shared__ float4 pred_sh[CAP_N];
    __shared__ float4 tgt_sh[CAP_M];
    __shared__ float  u_sh[CAP_M];
    __shared__ float  margin_sh[CAP_M];
    __shared__ int    gcol_sh[CAP_M];
    __shared__ int    vid_sh[CAP_M];
    __shared__ int    row4col_sh[CAP_N];   // col -> row (0-based), -1 free
    __shared__ int    col4row_sh[CAP_M];   // row -> col, -1 free
    __shared__ int    way_sh[CAP_N];       // predecessor row along shortest path
    __shared__ int    queue_sh[CAP_M + 4];
    __shared__ unsigned long long wpack_sh[2][NWARP];
    __shared__ float  f_red[NWARP];
    __shared__ int    s_k, s_nf, s_last;
    __shared__ double s_red[6 * NWARP];

    if (active) row4col_sh[col] = -1;
    if (tid < M) col4row_sh[tid] = -1;
    for (int j = tid; j < N; j += HT) pred_sh[j] = pred[b * N + j];
    for (int t = tid; t < M; t += HT) tgt_sh[t] = tgt[b * M + t];

    const float* mrow = mask + (size_t)b * M;
    if (wid == 0) {
        bool v0 = (lane < M) && (mrow[lane] > 0.5f);
        bool v1 = (32 + lane < M) && (mrow[32 + lane] > 0.5f);
        unsigned b0 = __ballot_sync(FULL, v0);
        unsigned b1 = __ballot_sync(FULL, v1);
        unsigned lm = (1u << lane) - 1u;
        if (v0) vid_sh[__popc(b0 & lm)] = lane;
        if (v1) vid_sh[__popc(b0) + __popc(b1 & lm)] = 32 + lane;
        if (lane == 0) {
            s_k = __popc(b0) + __popc(b1);
            g_k[b] = s_k;
        }
    }

    // --- cls log-softmax for this batch (whole block; runs before cost barrier) ---
    const float* xr = cls + (size_t)b * C;
    float cm = -FLT_MAX;
    for (int c = tid; c < C; c += HT) cm = fmaxf(cm, xr[c]);
    #pragma unroll
    for (int off = 16; off; off >>= 1)
        cm = fmaxf(cm, __shfl_xor_sync(FULL, cm, off));
    if (lane == 0) f_red[wid] = cm;
    __syncthreads();
    {
        float m0 = f_red[0];
        #pragma unroll
        for (int w = 1; w < NWARP; w++) m0 = fmaxf(m0, f_red[w]);
        cm = m0;
    }
    float cs = 0.0f;
    for (int c = tid; c < C; c += HT) cs += expf(xr[c] - cm);
    #pragma unroll
    for (int off = 16; off; off >>= 1)
        cs += __shfl_xor_sync(FULL, cs, off);
    __syncthreads();          // f_red reuse
    if (lane == 0) f_red[wid] = cs;
    __syncthreads();
    if (tid == 0) {
        float s0 = 0.0f;
        #pragma unroll
        for (int w = 0; w < NWARP; w++) s0 += f_red[w];
        g_cls[b] = (double)(cm + logf(s0) - xr[label[b]]);
    }
    int k = s_k;

    // --- build cost matrix in smem: cost[i][j] = 5*L1 - 2*GIoU ---
    for (int idx = tid; idx < k * N; idx += HT) {
        int i = idx / N;
        int j = idx - i * N;
        float4 p = pred_sh[j];
        float4 q = tgt_sh[vid_sh[i]];
        cost_sh[idx] = 5.0f * l1_cxcywh(p, q) - 2.0f * giou_cxcywh(p, q);
    }
    __syncthreads();

    // --- greedy: per-row (min1, argmin, min2) — rows striped over warps ---
    for (int i = wid; i < k; i += NWARP) {
        const float* crow = cost_sh + i * N;
        unsigned long long b1 = 0xFFFFFFFFFFFFFFFFull;
        unsigned long long b2 = 0xFFFFFFFFFFFFFFFFull;
        #pragma unroll
        for (int q = 0; q < 10; q++) {
            int c = lane + 32 * q;
            if (c < N) {
                unsigned long long pk = pack_vc(crow[c], (unsigned)c);
                if (pk < b1) { b2 = b1; b1 = pk; }
                else if (pk < b2) b2 = pk;
            }
        }
        #pragma unroll
        for (int off = 16; off; off >>= 1) {
            unsigned long long o1 = __shfl_xor_sync(FULL, b1, off);
            unsigned long long o2 = __shfl_xor_sync(FULL, b2, off);
            unsigned long long hi = (b1 < o1) ? o1 : b1;
            b1 = (b1 < o1) ? b1 : o1;
            unsigned long long lo2 = (b2 < o2) ? b2 : o2;
            b2 = (hi < lo2) ? hi : lo2;
        }
        if (lane == 0) {
            float m1 = unorder_f32((unsigned)(b1 >> 32));
            float m2 = unorder_f32((unsigned)(b2 >> 32));
            u_sh[i] = m1;
            gcol_sh[i] = (int)(b1 & 0xFFFFFFFFull);
            margin_sh[i] = m2 - m1;
        }
    }
    __syncthreads();

    // --- conflict resolution: contested column goes to max-margin row ---
    if (tid == 0) {
        int nf = 0;
        for (int i = 0; i < k; i++) {
            int c = gcol_sh[i];
            int own = row4col_sh[c];
            if (own < 0) {
                row4col_sh[c] = i; col4row_sh[i] = c;
            } else if (margin_sh[i] > margin_sh[own]) {
                row4col_sh[c] = i; col4row_sh[i] = c;
                col4row_sh[own] = -1;
                queue_sh[nf++] = own;
            } else {
                queue_sh[nf++] = i;
            }
        }
        s_nf = nf;
    }
    __syncthreads();
    int nf = s_nf;

    // --- block-wide SSP augmentation: ONE barrier per Dijkstra step ---
    float v = 0.0f;  // column dual (register; one col per thread)
    for (int qi = 0; qi < nf; qi++) {
        int cur = queue_sh[qi];
        float minv = INFINITY;
        int way = 0;
        bool inSC = false;
        int i_cur = cur;
        float base = -u_sh[cur];
        float mv;
        int sink;
        int par = 0;
        while (true) {
            unsigned key = 0xFFFFFFFFu;
            if (active && !inSC) {
                float r = base + cost_sh[i_cur * N + col] - v;
                if (r < minv) { minv = r; way = i_cur; }
                key = order_f32(minv);
            }
            unsigned kmin = __reduce_min_sync(FULL, key);
            unsigned cnd = (key == kmin) ? (unsigned)col : 0x7FFFFFFFu;
            unsigned cmin = __reduce_min_sync(FULL, cnd);
            if (lane == 0)
                wpack_sh[par][wid] = ((unsigned long long)kmin << 32) | cmin;
            __syncthreads();
            // pairwise tree fold of NWARP(=10) candidates
            unsigned long long c0 = wpack_sh[par][0];
            unsigned long long c1 = wpack_sh[par][1];
            unsigned long long c2 = wpack_sh[par][2];
            unsigned long long c3 = wpack_sh[par][3];
            unsigned long long c4 = wpack_sh[par][4];
            unsigned long long c5 = wpack_sh[par][5];
            unsigned long long c6 = wpack_sh[par][6];
            unsigned long long c7 = wpack_sh[par][7];
            unsigned long long c8 = wpack_sh[par][8];
            unsigned long long c9 = wpack_sh[par][9];
            c0 = (c1 < c0) ? c1 : c0;
            c2 = (c3 < c2) ? c3 : c2;
            c4 = (c5 < c4) ? c5 : c4;
            c6 = (c7 < c6) ? c7 : c6;
            c8 = (c9 < c8) ? c9 : c8;
            c0 = (c2 < c0) ? c2 : c0;
            c4 = (c6 < c4) ? c6 : c4;
            c0 = (c4 < c0) ? c4 : c0;
            unsigned long long best = (c8 < c0) ? c8 : c0;
            par ^= 1;
            float d = unorder_f32((unsigned)(best >> 32));
            int j0 = (int)(best & 0xFFFFFFFFull);
            if (col == j0) { inSC = true; way_sh[col] = way; }
            int r0 = row4col_sh[j0];       // uniform broadcast read
            if (r0 < 0) { mv = d; sink = j0; break; }
            base = d - u_sh[r0];
            i_cur = r0;
        }
        __syncthreads();   // way_sh[sink] + loop reads done before dual/assign updates
        // dual updates (once per augmentation)
        if (active && inSC) {
            float diff = mv - minv;
            v -= diff;
            int r = row4col_sh[col];
            if (r >= 0) u_sh[r] += diff;   // distinct r per col
        }
        if (tid == 0) u_sh[cur] += mv;
        __syncthreads();   // duals settled before assignment rewiring
        if (tid == 0) {
            int j = sink;
            while (true) {
                int i = way_sh[j];
                row4col_sh[j] = i;
                int jn = col4row_sh[i];
                col4row_sh[i] = j;
                if (i == cur) break;
                j = jn;
            }
        }
        __syncthreads();
    }

    // --- pair losses + BCE (one column per thread) ---
    double bb = 0.0, gg = 0.0, ab = 0.0, ag = 0.0, bm = 0.0, ba = 0.0;
    if (active) {
        int r = row4col_sh[col];
        float ot = (r >= 0) ? 1.0f : 0.0f;
        bm = (double)bce_f(obj[b * N + col], ot);
        for (int l = 0; l < L; l++)
            ba += (double)bce_f(aux_obj[((size_t)l * B + b) * N + col], ot);
        if (r >= 0) {
            float4 p = pred_sh[col];
            float4 t = tgt_sh[vid_sh[r]];
            bb = (double)l1_cxcywh(p, t);
            gg = (double)(1.0f - giou_cxcywh(p, t));
            for (int l = 0; l < L; l++) {
                float4 a = aux_pred[((size_t)l * B + b) * N + col];
                ab += (double)l1_cxcywh(a, t);
                ag += (double)(1.0f - giou_cxcywh(a, t));
            }
        }
    }
    #pragma unroll
    for (int off = 16; off; off >>= 1) {
        bb += __shfl_xor_sync(FULL, bb, off);
        gg += __shfl_xor_sync(FULL, gg, off);
        ab += __shfl_xor_sync(FULL, ab, off);
        ag += __shfl_xor_sync(FULL, ag, off);
        bm += __shfl_xor_sync(FULL, bm, off);
        ba += __shfl_xor_sync(FULL, ba, off);
    }
    if (lane == 0) {
        s_red[wid] = bb;
        s_red[NWARP + wid] = gg;
        s_red[2 * NWARP + wid] = ab;
        s_red[3 * NWARP + wid] = ag;
        s_red[4 * NWARP + wid] = bm;
        s_red[5 * NWARP + wid] = ba;
    }
    __syncthreads();
    if (tid < 6) {
        double t0 = 0.0;
        #pragma unroll
        for (int w = 0; w < NWARP; w++) t0 += s_red[tid * NWARP + w];
        g_pair[b * 6 + tid] = t0;
    }

    // --- last block folds everything into the output scalar ---
    if (tid == 0) {
        __threadfence();
        unsigned t = atomicAdd(&g_sem, 1u);
        s_last = (t == (unsigned)(B - 1)) ? 1 : 0;
    }
    __syncthreads();
    if (!s_last) return;
    __threadfence();
    if (tid == 0) {
        double nb = 0.0, clsl = 0.0, bbox = 0.0, gi = 0.0;
        double abx = 0.0, agx = 0.0, objs = 0.0, aobj = 0.0;
        for (int bi = 0; bi < B; bi++) {
            nb   += (double)g_k[bi];
            clsl += g_cls[bi];
            bbox += g_pair[bi * 6 + 0];
            gi   += g_pair[bi * 6 + 1];
            abx  += g_pair[bi * 6 + 2];
            agx  += g_pair[bi * 6 + 3];
            objs += g_pair[bi * 6 + 4];
            aobj += g_pair[bi * 6 + 5];
        }
        if (nb < 1.0) nb = 1.0;
        double BN = (double)B * (double)N;
        double tot = clsl / (double)B
                   + 5.0 * bbox / nb
                   + 2.0 * gi / nb
                   + objs / BN
                   + (5.0 * abx / nb + 2.0 * agx / nb + aobj / BN) * 0.5 / (double)L;
        out[0] = (float)tot;
        g_sem = 0u;  // reset for next replay
    }
}

// ---------------- launch ----------------
extern "C" void kernel_launch(void* const* d_in, const int* in_sizes, int n_in,
                              void* d_out, int out_size)
{
    const float* cls      = (const float*)d_in[0];
    const int*   label    = (const int*)d_in[1];
    const float* pred     = (const float*)d_in[2];
    const float* obj      = (const float*)d_in[3];
    const float* tgt      = (const float*)d_in[4];
    const float* mask     = (const float*)d_in[5];
    const float* aux_pred = (const float*)d_in[6];
    const float* aux_obj  = (const float*)d_in[7];

    int B = in_sizes[1];
    int C = in_sizes[0] / B;
    int N = in_sizes[3] / B;
    int M = in_sizes[5] / B;
    int L = in_sizes[6] / (B * N * 4);
    float* out = (float*)d_out;

    size_t smem = (size_t)CAP_M * CAP_N * sizeof(float);  // 72000 B
    static int attr_set = 0;
    if (!attr_set) {
        cudaFuncSetAttribute(detr_kernel,
                             cudaFuncAttributeMaxDynamicSharedMemorySize, (int)smem);
        attr_set = 1;
    }

    detr_kernel<<<B, HT, smem>>>(mask, (const float4*)pred, (const float4*)tgt,
                                 (const float4*)aux_pred, obj, aux_obj,
                                 cls, label, out, B, N, M, L, C);
}